// round 10
// baseline (speedup 1.0000x reference)
#include <cuda_runtime.h>
#include <cuda_bf16.h>
#include <cstddef>
#include <cstdint>

// Problem constants (fixed by the dataset)
#define BATCH 64
#define LSEQ  512
#define DIN   256
#define HDIM  256
#define H3    768
#define ADIM  128
#define DEPTH 4
#define NROWS (LSEQ * BATCH)   // 32768

#define CLUSTER_NCTAS 8
#define ROWS_PER_CTA  96       // 768 / 8
#define NBAT          4
#define NCLU          16
#define SCAN_THREADS  896
#define GOUT_F4       100      // 96 data float4 + 8 stats floats + pad
#define CLUBUF        (CLUSTER_NCTAS * GOUT_F4 * 4)   // 3200 floats per parity
#define SL_STRIDE     520      // steplist ints per batch (513 used)

// SMEM weight layout: row r = 72 float4 (8 kq-blocks of 9: 8 data + 1 pad)
#define WROW_F4  72
// hT layout: float4 per k (4 batches), 33-f4 blocks (32 data + 1 pad)
#define HT_F4(k)        ((((k) >> 5) * 33) + ((k) & 31))
#define HT_FLT(k, b)    ((((k) >> 5) * 132) + (((k) & 31) * 4) + (b))

// ---------------- scratch (device globals; no allocation allowed) -------------
__device__ float g_h0  [(size_t)NROWS * HDIM];
__device__ float g_h1  [(size_t)NROWS * HDIM];
__device__ float g_xp  [(size_t)NROWS * H3];
__device__ float g_xa  [(size_t)NROWS * ADIM];
__device__ float g_Ut  [(size_t)H3 * HDIM];       // U^T (768x256)
__device__ float g_hp  [(size_t)NCLU * 2 * CLUBUF];
__device__ int   g_steplist[BATCH * SL_STRIDE];
__device__ int   g_src  [BATCH * LSEQ];
__device__ int   g_nsteps[BATCH];
__device__ unsigned char g_mask[BATCH * LSEQ];

// ---------------------------------- helpers ----------------------------------
__device__ __forceinline__ float warp_sum(float v) {
#pragma unroll
    for (int o = 16; o > 0; o >>= 1) v += __shfl_down_sync(0xffffffffu, v, o);
    return v;
}
__device__ __forceinline__ void fma2(unsigned long long& d, unsigned long long a,
                                     unsigned long long b) {
    asm("fma.rn.f32x2 %0, %1, %2, %0;" : "+l"(d) : "l"(a), "l"(b));
}
__device__ __forceinline__ unsigned long long pk(float lo, float hi) {
    unsigned long long r;
    asm("mov.b64 %0, {%1, %2};" : "=l"(r) : "f"(lo), "f"(hi));
    return r;
}
__device__ __forceinline__ float2 upk(unsigned long long v) {
    float2 r;
    asm("mov.b64 {%0, %1}, %2;" : "=f"(r.x), "=f"(r.y) : "l"(v));
    return r;
}
__device__ __forceinline__ float sum4(float4 v) { return (v.x + v.y) + (v.z + v.w); }
__device__ __forceinline__ float sq4(float4 v)  { return (v.x * v.x + v.y * v.y) + (v.z * v.z + v.w * v.w); }
__device__ __forceinline__ uint32_t smem_u32(const void* p) {
    uint32_t a;
    asm("{ .reg .u64 t; cvta.to.shared.u64 t, %1; cvt.u32.u64 %0, t; }" : "=r"(a) : "l"(p));
    return a;
}
__device__ __forceinline__ void mbar_wait_cluster(uint32_t addr, uint32_t parity) {
    uint32_t done;
    asm volatile(
        "{\n\t.reg .pred p;\n\t"
        "mbarrier.try_wait.parity.acquire.cluster.shared::cta.b64 p, [%1], %2;\n\t"
        "selp.b32 %0, 1, 0, p;\n\t}"
        : "=r"(done) : "r"(addr), "r"(parity) : "memory");
    while (!done) {
        asm volatile(
            "{\n\t.reg .pred p;\n\t"
            "mbarrier.try_wait.parity.acquire.cluster.shared::cta.b64 p, [%1], %2, 0x989680;\n\t"
            "selp.b32 %0, 1, 0, p;\n\t}"
            : "=r"(done) : "r"(addr), "r"(parity) : "memory");
    }
}

// ----------------- prep: U transpose + mask copy + depth-0 plan ---------------
__global__ void prep_fused(const float* __restrict__ U,
                           const unsigned char* __restrict__ m8) {
    int k = blockIdx.x;
    if (k < H3) {
        int i = threadIdx.x;  // 0..255
        g_Ut[(size_t)k * HDIM + i] = U[(size_t)i * H3 + k];
        return;
    }
    __shared__ unsigned char smm[BATCH * LSEQ];
    __shared__ int mode;
    int t = threadIdx.x;
    if (t == 0) {
        int nz = 0;
        for (int i = 0; i < 64; i++) nz |= m8[4 * i + 1] | m8[4 * i + 2] | m8[4 * i + 3];
        mode = nz ? 1 : 0;
    }
    __syncthreads();
    if (mode) {
        for (int i = t; i < BATCH * LSEQ; i += blockDim.x) {
            unsigned char v = m8[i] ? 1 : 0;
            g_mask[i] = v; smm[i] = v;
        }
    } else {
        const int* m32 = (const int*)m8;
        for (int i = t; i < BATCH * LSEQ; i += blockDim.x) {
            unsigned char v = m32[i] ? 1 : 0;
            g_mask[i] = v; smm[i] = v;
        }
    }
    __syncthreads();
    if (t < BATCH) {
        int b = t, n = 0, src = -1;
        for (int l = 0; l < LSEQ; l++) {
            if (smm[b * LSEQ + l]) { g_steplist[b * SL_STRIDE + n] = l; n++; src = l; }
            else                   { g_src[b * LSEQ + l] = src; }
        }
        g_nsteps[b] = n;
        for (int i = n; i <= LSEQ; i++) g_steplist[b * SL_STRIDE + i] = -1;
    }
}

// ---------------- plan (d>=1): unmasked-step list + fill sources --------------
__global__ void plan_kernel() {
    int b = blockIdx.x, t = threadIdx.x;   // 64 blocks x 32 threads
    __shared__ unsigned char m[LSEQ];
    __shared__ int sn;
    for (int i = t; i < LSEQ; i += 32) m[i] = g_mask[b * LSEQ + i];
    __syncwarp();
    if (t == 0) {
        int n = 0, src = -1;
        for (int l = 0; l < LSEQ; l++) {
            if (m[l]) { g_steplist[b * SL_STRIDE + n] = l; n++; src = l; }
            else      { g_src[b * LSEQ + l] = src; }
        }
        g_nsteps[b] = n;
        sn = n;
    }
    __syncwarp();
    for (int i = sn + t; i <= LSEQ; i += 32) g_steplist[b * SL_STRIDE + i] = -1;
}

// ------------------------------- tiled SGEMM (f32x2) --------------------------
template <int MODE>
__global__ void __launch_bounds__(256) sgemm_kernel(
    const float* __restrict__ A, const float* __restrict__ Bm,
    const float* __restrict__ bias, float* __restrict__ C, int N) {
    const int K = 256;
    __shared__ __align__(16) float Ast[16][68];
    __shared__ __align__(16) float Bs[16][64];
    int t  = threadIdx.x;
    int m0 = blockIdx.y * 64;
    int n0 = blockIdx.x * 64;
    int ty = t >> 4, tx = t & 15;

    unsigned long long acc2[4][2];
#pragma unroll
    for (int i = 0; i < 4; i++) { acc2[i][0] = 0ull; acc2[i][1] = 0ull; }

    int ar = t >> 2;
    int ak = (t & 3) * 4;
    int arow = m0 + ar;
    const float* Aptr;
    if (MODE == 1) {
        int b = arow & 63, l = arow >> 6;
        Aptr = A + ((size_t)b * LSEQ + l) * K;
    } else if (MODE == 2) {
        Aptr = A + (size_t)(arow - 64) * K;
    } else {
        Aptr = A + (size_t)arow * K;
    }
    const bool avalid = (MODE != 2) || (arow >= 64);
    int bk = t >> 4;
    int bn = (t & 15) * 4;

    for (int k0 = 0; k0 < K; k0 += 16) {
        float4 av = make_float4(0.f, 0.f, 0.f, 0.f);
        if (avalid) av = *(const float4*)(Aptr + k0 + ak);
        Ast[ak + 0][ar] = av.x;
        Ast[ak + 1][ar] = av.y;
        Ast[ak + 2][ar] = av.z;
        Ast[ak + 3][ar] = av.w;
        *(float4*)(&Bs[bk][bn]) = *(const float4*)(Bm + (size_t)(k0 + bk) * N + n0 + bn);
        __syncthreads();
#pragma unroll
        for (int kk = 0; kk < 16; kk++) {
            float4 a  = *(const float4*)(&Ast[kk][ty * 4]);
            float4 bb = *(const float4*)(&Bs[kk][tx * 4]);
            unsigned long long b01 = pk(bb.x, bb.y), b23 = pk(bb.z, bb.w);
            unsigned long long ax = pk(a.x, a.x), ay = pk(a.y, a.y);
            unsigned long long az = pk(a.z, a.z), aw = pk(a.w, a.w);
            fma2(acc2[0][0], ax, b01); fma2(acc2[0][1], ax, b23);
            fma2(acc2[1][0], ay, b01); fma2(acc2[1][1], ay, b23);
            fma2(acc2[2][0], az, b01); fma2(acc2[2][1], az, b23);
            fma2(acc2[3][0], aw, b01); fma2(acc2[3][1], aw, b23);
        }
        __syncthreads();
    }
#pragma unroll
    for (int i = 0; i < 4; i++) {
        int row = m0 + ty * 4 + i;
        float2 v01 = upk(acc2[i][0]), v23 = upk(acc2[i][1]);
        float4 v;
        v.x = v01.x; v.y = v01.y; v.z = v23.x; v.w = v23.y;
        if (MODE != 2 && bias) {
            v.x += bias[n0 + tx * 4 + 0];
            v.y += bias[n0 + tx * 4 + 1];
            v.z += bias[n0 + tx * 4 + 2];
            v.w += bias[n0 + tx * 4 + 3];
        }
        float4* cp = (float4*)(&C[(size_t)row * N + n0 + tx * 4]);
        if (MODE == 2) {
            float4 o = *cp;
            v.x += o.x; v.y += o.y; v.z += o.z; v.w += o.w;
        }
        *cp = v;
    }
}

// -------------------- fill: masked h_out rows = carried h ---------------------
__global__ void fill_kernel(float* __restrict__ hout) {
    int l = blockIdx.x, b = blockIdx.y, t = threadIdx.x;   // 64 threads
    if (g_mask[b * LSEQ + l]) return;
    int src = g_src[b * LSEQ + l];
    float4 v = make_float4(0.f, 0.f, 0.f, 0.f);
    if (src >= 0) v = ((const float4*)hout)[((size_t)src * BATCH + b) * 64 + t];
    ((float4*)hout)[((size_t)l * BATCH + b) * 64 + t] = v;
}

// -------------------- head: bulk action/policy + next mask --------------------
__global__ void head_kernel(int d, const float* __restrict__ lin,
                            const float* __restrict__ ba1,
                            const float* __restrict__ Wa2,
                            const float* __restrict__ ba2,
                            const float* __restrict__ hout,
                            float* __restrict__ out, int out_size) {
    int r = blockIdx.x;            // (l,b) row: r = l*64 + b
    int l = r >> 6, b = r & 63;
    int t = threadIdx.x;           // 128
    __shared__ float s[8];

    float v = tanhf(lin[(size_t)r * ADIM + t] + ba1[t]);
    float p0 = warp_sum(v * Wa2[2 * t]);
    float p1 = warp_sum(v * Wa2[2 * t + 1]);
    if ((t & 31) == 0) { s[(t >> 5) * 2] = p0; s[(t >> 5) * 2 + 1] = p1; }

    if (d == DEPTH - 1 && l == LSEQ - 1 && out_size >= BATCH * HDIM) {
        const float* hr = hout + ((size_t)(LSEQ - 1) * BATCH + b) * HDIM;
        out[b * HDIM + t]       = hr[t];
        out[b * HDIM + 128 + t] = hr[128 + t];
    }
    __syncthreads();
    if (t == 0) {
        float l0 = s[0] + s[2] + s[4] + s[6] + ba2[0];
        float l1 = s[1] + s[3] + s[5] + s[7] + ba2[1];
        unsigned char mt = g_mask[b * LSEQ + l];
        unsigned char act = ((l1 > l0) && mt) ? 1 : 0;
        g_mask[b * LSEQ + l] = act;      // next-depth mask
        if (out_size >= 409600) {
            float m = fmaxf(l0, l1);
            float e0 = expf(l0 - m), e1 = expf(l1 - m);
            float inv = 1.0f / (e0 + e1);
            size_t ai = (size_t)BATCH * HDIM + ((size_t)(b * DEPTH + d)) * LSEQ + l;
            out[ai] = act ? 1.0f : 0.0f;
            size_t pi = (size_t)BATCH * HDIM + (size_t)BATCH * DEPTH * LSEQ +
                        (((size_t)(b * DEPTH + d)) * LSEQ + l) * 2;
            out[pi]     = e0 * inv;
            out[pi + 1] = e1 * inv;
        }
    }
}

// -------- cluster scan: 4-way distributed gates + DSMEM h exchange ------------
// Rank r computes gates ONLY for batch bb=r&3 (256 items, 5 MUFU each) and
// pushes its 1KB h-slice to the 3 partners in its group (r&4) via
// st.shared::cluster; partner sync = 4-arrival mbarrier pair (parity).
// Matvec/partials exchange keeps the single cluster barrier + L2 gout.
__global__ void __cluster_dims__(CLUSTER_NCTAS, 1, 1) __launch_bounds__(SCAN_THREADS, 1)
scan7_kernel(const float* __restrict__ bg,
             const float* __restrict__ gammas,
             const float* __restrict__ betas,
             float* __restrict__ hout) {
    extern __shared__ __align__(16) float sm[];
    // sm[0..3]: two mbarriers (2 x u64)
    float* Wsm   = sm + 4;                            // 27648
    float* s_hT  = Wsm  + ROWS_PER_CTA * WROW_F4 * 4; // 1056
    float* s_hp  = s_hT + 1056;                       // 772 (768 + pad)
    float* s_xpa = s_hp + 772;                        // 2*768 = 1536
    float* c_g0  = s_xpa + 2 * H3;                    // 768
    float* c_b0  = c_g0 + H3;
    float* c_g1  = c_b0 + H3;
    float* c_b1  = c_g1 + H3;
    float* c_bg  = c_b1 + H3;
    float* s_lnA = c_bg + H3;                         // 24*8 = 192
    float* s_stat= s_lnA + 192;                       // 4 (mu, rstd used)
    float* s_xscr= s_stat + 4;                        // 8 (4 warps x 2)
    float* s_xst = s_xscr + 8;                        // 4 (2 par x (mu, rstd))
    int*   s_lb  = (int*)(s_xst + 4);                 // 8 (2 par x 4 batches)
    uint32_t* s_rht = (uint32_t*)(s_lb + 8);          // 4 remote s_hT bases

    const int t    = threadIdx.x;
    const int rank = blockIdx.x & (CLUSTER_NCTAS - 1);
    const int clu  = blockIdx.x >> 3;
    const int b0   = clu * NBAT;
    const int lane = t & 31, wid = t >> 5;
    const int bb   = rank & 3;          // owned batch
    const int g0r  = rank & 4;          // group base rank

    const uint32_t mb = smem_u32(sm);   // mbar[0]=mb, mbar[1]=mb+8
    if (t == 0) {
        asm volatile("mbarrier.init.shared.b64 [%0], %1;" :: "r"(mb),     "r"(4u) : "memory");
        asm volatile("mbarrier.init.shared.b64 [%0], %1;" :: "r"(mb + 8), "r"(4u) : "memory");
    }
    if (t < 4) {
        uint32_t ra;
        uint32_t hta = smem_u32(s_hT);
        asm("mapa.shared::cluster.u32 %0, %1, %2;" : "=r"(ra) : "r"(hta), "r"(g0r + t));
        s_rht[t] = ra;
    }

    // ---- weight slice (rows 96*rank..+95 of U^T) into padded layout ----
    {
        const float4* src = (const float4*)(g_Ut + (size_t)(ROWS_PER_CTA * rank) * HDIM);
        float4* dst = (float4*)Wsm;
        for (int i = t; i < ROWS_PER_CTA * 64; i += SCAN_THREADS) {
            int row = i >> 6, c4 = i & 63;
            dst[row * WROW_F4 + (c4 >> 3) * 9 + (c4 & 7)] = src[(size_t)row * 64 + c4];
        }
    }
    for (int i = t; i < H3; i += SCAN_THREADS) {
        c_g0[i] = gammas[i];
        c_b0[i] = betas[i];
        c_g1[i] = gammas[H3 + i];
        c_b1[i] = betas[H3 + i];
        c_bg[i] = bg[i];
    }
    for (int i = t; i < 1056; i += SCAN_THREADS) s_hT[i] = 0.0f;

    int maxit = 0;
#pragma unroll
    for (int i = 0; i < 4; i++) {
        int n = g_nsteps[b0 + i];
        maxit = (n > maxit) ? n : maxit;
    }
    if (t < 4) s_lb[t] = g_steplist[(b0 + t) * SL_STRIDE];
    __syncthreads();

    // prologue: load own-batch xp for it=0 + its LN stats
    const int lb0 = s_lb[bb];
    if (t < 192 && lb0 >= 0)
        ((float4*)s_xpa)[t] =
            *((const float4*)g_xp + ((size_t)lb0 * BATCH + b0 + bb) * 192 + t);
    __syncthreads();
    if (wid == 0 && lb0 >= 0) {
        float s = 0.f, q = 0.f;
#pragma unroll
        for (int j = 0; j < 24; j++) { float v = s_xpa[lane + 32 * j]; s += v; q += v * v; }
        s = warp_sum(s); q = warp_sum(q);
        if (lane == 0) {
            float mu = s * (1.0f / 768.0f), var = q * (1.0f / 768.0f) - mu * mu;
            s_xst[0] = mu; s_xst[1] = rsqrtf(var + 1e-5f);
        }
    }
    __syncthreads();

    const int r_ = t >> 3, kq = t & 7;
    const float4* wf = (const float4*)Wsm + r_ * WROW_F4 + kq * 9;
    const float4* ht = (const float4*)s_hT;
    float* gbase = g_hp + (size_t)clu * (2 * CLUBUF);

    for (int it = 0; it < maxit; ++it) {
        const int par = it & 1, nxt = par ^ 1;
        float* gout = gbase + par * CLUBUF;

        // ================ phase A: matvec + LN partials | helpers prefetch ====
        float4 pf0, pf1;
        if (t < 768) {
            unsigned long long a01 = 0ull, a23 = 0ull;
#pragma unroll
            for (int i = 0; i < 8; i++) {
                float4 w  = wf[i];
                float4 h0 = ht[kq * 33 + i * 4 + 0];
                float4 h1 = ht[kq * 33 + i * 4 + 1];
                float4 h2 = ht[kq * 33 + i * 4 + 2];
                float4 h3 = ht[kq * 33 + i * 4 + 3];
                fma2(a01, pk(w.x, w.x), pk(h0.x, h0.y)); fma2(a23, pk(w.x, w.x), pk(h0.z, h0.w));
                fma2(a01, pk(w.y, w.y), pk(h1.x, h1.y)); fma2(a23, pk(w.y, w.y), pk(h1.z, h1.w));
                fma2(a01, pk(w.z, w.z), pk(h2.x, h2.y)); fma2(a23, pk(w.z, w.z), pk(h2.z, h2.w));
                fma2(a01, pk(w.w, w.w), pk(h3.x, h3.y)); fma2(a23, pk(w.w, w.w), pk(h3.z, h3.w));
            }
            float2 v01 = upk(a01), v23 = upk(a23);
            float d0 = v01.x, d1 = v01.y, d2 = v23.x, d3 = v23.y;
#pragma unroll
            for (int m = 1; m < 8; m <<= 1) {
                d0 += __shfl_xor_sync(0xffffffffu, d0, m);
                d1 += __shfl_xor_sync(0xffffffffu, d1, m);
                d2 += __shfl_xor_sync(0xffffffffu, d2, m);
                d3 += __shfl_xor_sync(0xffffffffu, d3, m);
            }
            if (kq == 0) {
                float4 o; o.x = d0; o.y = d1; o.z = d2; o.w = d3;
                ((float4*)gout)[rank * GOUT_F4 + r_] = o;
            }
            float q0 = d0 * d0, q1 = d1 * d1, q2 = d2 * d2, q3 = d3 * d3;
#pragma unroll
            for (int m = 8; m <= 16; m <<= 1) {
                d0 += __shfl_xor_sync(0xffffffffu, d0, m);
                d1 += __shfl_xor_sync(0xffffffffu, d1, m);
                d2 += __shfl_xor_sync(0xffffffffu, d2, m);
                d3 += __shfl_xor_sync(0xffffffffu, d3, m);
                q0 += __shfl_xor_sync(0xffffffffu, q0, m);
                q1 += __shfl_xor_sync(0xffffffffu, q1, m);
                q2 += __shfl_xor_sync(0xffffffffu, q2, m);
                q3 += __shfl_xor_sync(0xffffffffu, q3, m);
            }
            if (lane == 0) {
                s_lnA[wid * 8 + 0] = d0; s_lnA[wid * 8 + 1] = d1;
                s_lnA[wid * 8 + 2] = d2; s_lnA[wid * 8 + 3] = d3;
                s_lnA[wid * 8 + 4] = q0; s_lnA[wid * 8 + 5] = q1;
                s_lnA[wid * 8 + 6] = q2; s_lnA[wid * 8 + 7] = q3;
            }
        } else {
            int u = t - 768;     // 0..127
            int lbn = g_steplist[(b0 + bb) * SL_STRIDE + it + 1];
            if (u == 0) s_lb[nxt * 4 + bb] = lbn;
            pf0 = make_float4(0.f, 0.f, 0.f, 0.f);
            pf1 = make_float4(0.f, 0.f, 0.f, 0.f);
            if (lbn >= 0) {
                const float4* xr = (const float4*)g_xp +
                                   ((size_t)lbn * BATCH + b0 + bb) * 192;
                pf0 = xr[u];
                if (u < 64) pf1 = xr[128 + u];
            }
        }
        __syncthreads();
        if (t < 8) {
            float acc = 0.f;
#pragma unroll
            for (int w = 0; w < 24; w++) acc += s_lnA[w * 8 + t];
            gout[rank * GOUT_F4 * 4 + 384 + t] = acc;
        }

        asm volatile("barrier.cluster.arrive.aligned;" ::: "memory");
        asm volatile("barrier.cluster.wait.aligned;" ::: "memory");

        // ============ phase B: own-batch hp gather | stats | pf store =========
        if (t < 768) {
            int rank_r = t / 96, wrow_r = t - 96 * rank_r;
            s_hp[t] = __ldcv(&gout[(rank_r * GOUT_F4 + wrow_r) * 4 + bb]);
        }
        if (t < 16) {   // hp LN mu/rstd for own batch from gout stats
            float v = __ldcv(gout + (t & 7) * GOUT_F4 * 4 + 384 + ((t >= 8) ? 4 + bb : bb));
            v += __shfl_xor_sync(0x0000ffffu, v, 1);
            v += __shfl_xor_sync(0x0000ffffu, v, 2);
            v += __shfl_xor_sync(0x0000ffffu, v, 4);
            float Q = __shfl_sync(0x0000ffffu, v, 8);
            if (t == 0) {
                float mu  = v * (1.0f / 768.0f);
                float var = Q * (1.0f / 768.0f) - mu * mu;
                s_stat[0] = mu;
                s_stat[1] = rsqrtf(var + 1e-5f);
            }
        }
        if (t >= 768) {
            int u = t - 768;
            float* xd = s_xpa + nxt * H3;
            ((float4*)xd)[u] = pf0;
            float s = sum4(pf0), q = sq4(pf0);
            if (u < 64) { ((float4*)xd)[128 + u] = pf1; s += sum4(pf1); q += sq4(pf1); }
            s = warp_sum(s); q = warp_sum(q);
            if (lane == 0) {
                int w = wid - 24;
                s_xscr[w * 2] = s; s_xscr[w * 2 + 1] = q;
            }
        }
        __syncthreads();

        // ============ phase C: gates for OWN batch (t<256) ====================
        if (t < 256) {
            int col = t;
            int lb = s_lb[par * 4 + bb];
            if (lb >= 0) {
                float mu = s_stat[0], rs = s_stat[1];
                float mux = s_xst[par * 2], rsx = s_xst[par * 2 + 1];
                const float* xr = s_xpa + par * H3;
                float x0 = c_g0[col]       * (xr[col]       - mux) * rsx + c_b0[col];
                float x1 = c_g0[col + 256] * (xr[col + 256] - mux) * rsx + c_b0[col + 256];
                float x2 = c_g0[col + 512] * (xr[col + 512] - mux) * rsx + c_b0[col + 512];
                float hp0 = (s_hp[col]       - mu) * rs * c_g1[col]       + c_b1[col];
                float hp1 = (s_hp[col + 256] - mu) * rs * c_g1[col + 256] + c_b1[col + 256];
                float hp2 = (s_hp[col + 512] - mu) * rs * c_g1[col + 512] + c_b1[col + 512];
                // shared-RCP sigmoids + tanh (5 MUFU total)
                float ea = fminf(__expf(-(x0 + hp0 + c_bg[col])),       3.0e7f);
                float eb = fminf(__expf(-(x1 + hp1 + c_bg[col + 256])), 3.0e7f);
                float pa = 1.0f + ea, pb = 1.0f + eb;
                float inv = __fdividef(1.0f, pa * pb);
                float r = pb * inv;                 // sigmoid(A0)
                float z = pa * inv;                 // sigmoid(A1)
                float A2 = x2 + r * hp2 + c_bg[col + 512];
                float ec = fminf(__expf(-2.0f * A2), 3.0e7f);
                float th = (1.0f - ec) * __fdividef(1.0f, 1.0f + ec);
                float hold = s_hT[HT_FLT(col, bb)];
                float ho = z * hold + (1.0f - z) * th;
                // local + 3 remote h stores
                s_hT[HT_FLT(col, bb)] = ho;
                uint32_t off = (uint32_t)(HT_FLT(col, bb) * 4);
#pragma unroll
                for (int rr = 0; rr < 4; rr++) {
                    if ((g0r + rr) != rank) {
                        asm volatile("st.shared::cluster.f32 [%0], %1;"
                                     :: "r"(s_rht[rr] + off), "f"(ho) : "memory");
                    }
                }
                if (rank < 4)
                    hout[((size_t)lb * BATCH + b0 + bb) * HDIM + col] = ho;
            }
        } else if (t == 768) {
            float S = s_xscr[0] + s_xscr[2] + s_xscr[4] + s_xscr[6];
            float Q = s_xscr[1] + s_xscr[3] + s_xscr[5] + s_xscr[7];
            float mu = S * (1.0f / 768.0f), var = Q * (1.0f / 768.0f) - mu * mu;
            s_xst[nxt * 2] = mu; s_xst[nxt * 2 + 1] = rsqrtf(var + 1e-5f);
        }
        __syncthreads();   // all remote stores issued; local smem stable

        if (t == 0) {
            asm volatile("fence.acq_rel.cluster;" ::: "memory");
            uint32_t lbad = mb + (uint32_t)par * 8u;
#pragma unroll
            for (int rr = 0; rr < 4; rr++) {
                asm volatile(
                    "{\n\t.reg .b32 ra;\n\t"
                    "mapa.shared::cluster.u32 ra, %0, %1;\n\t"
                    "mbarrier.arrive.release.cluster.shared::cluster.b64 _, [ra];\n\t}"
                    :: "r"(lbad), "r"(g0r + rr) : "memory");
            }
        }
        mbar_wait_cluster(mb + (uint32_t)par * 8u, (uint32_t)((it >> 1) & 1));
    }

    // no CTA may exit while peers might still store into its SMEM
    asm volatile("barrier.cluster.arrive.aligned;" ::: "memory");
    asm volatile("barrier.cluster.wait.aligned;" ::: "memory");
}

// --------------------------------- launcher ----------------------------------
extern "C" void kernel_launch(void* const* d_in, const int* in_sizes, int n_in,
                              void* d_out, int out_size) {
    const float* x     = (const float*)d_in[0];
    const unsigned char* mask = (const unsigned char*)d_in[1];
    const float* W_emb = (const float*)d_in[2];
    const float* b_emb = (const float*)d_in[3];
    const float* W     = (const float*)d_in[4];
    const float* U     = (const float*)d_in[5];
    const float* bgate = (const float*)d_in[6];
    const float* Wa1   = (const float*)d_in[7];
    const float* Ua1   = (const float*)d_in[8];
    const float* ba1   = (const float*)d_in[9];
    const float* Wa2   = (const float*)d_in[10];
    const float* ba2   = (const float*)d_in[11];
    const float* gammas = (const float*)d_in[12];
    const float* betas  = (const float*)d_in[13];
    float* out = (float*)d_out;

    float *h0, *h1, *xp, *xa;
    cudaGetSymbolAddress((void**)&h0, g_h0);
    cudaGetSymbolAddress((void**)&h1, g_h1);
    cudaGetSymbolAddress((void**)&xp, g_xp);
    cudaGetSymbolAddress((void**)&xa, g_xa);

    const int scan_smem =
        (4 + ROWS_PER_CTA * WROW_F4 * 4 + 1056 + 772 + 2 * H3 +
         5 * H3 + 192 + 4 + 8 + 4 + 8 + 4) * 4;
    static int attr_done = 0;
    if (!attr_done) {
        cudaFuncSetAttribute(scan7_kernel, cudaFuncAttributeMaxDynamicSharedMemorySize, scan_smem);
        attr_done = 1;
    }

    // launch order: 0 prep, 1 embed, 2 gemmH3, 3 SCAN (profiled), ...
    prep_fused<<<H3 + 1, HDIM>>>(U, mask);
    sgemm_kernel<1><<<dim3(HDIM / 64, NROWS / 64), 256>>>(x, W_emb, b_emb, h0, HDIM);

    for (int d = 0; d < DEPTH; d++) {
        float* hin  = (d & 1) ? h1 : h0;
        float* hout = (d & 1) ? h0 : h1;
        sgemm_kernel<0><<<dim3(H3 / 64, NROWS / 64), 256>>>(hin, W, nullptr, xp, H3);
        scan7_kernel<<<NCLU * CLUSTER_NCTAS, SCAN_THREADS, scan_smem>>>(
            bgate, gammas, betas, hout);
        sgemm_kernel<0><<<dim3(ADIM / 64, NROWS / 64), 256>>>(hin, Wa1, nullptr, xa, ADIM);
        fill_kernel<<<dim3(LSEQ, BATCH), 64>>>(hout);
        sgemm_kernel<2><<<dim3(ADIM / 64, NROWS / 64), 256>>>(hout, Ua1, nullptr, xa, ADIM);
        head_kernel<<<NROWS, 128>>>(d, xa, ba1, Wa2, ba2, hout, out, out_size);
        if (d < DEPTH - 1) plan_kernel<<<BATCH, 32>>>();
    }
}

// round 11
// speedup vs baseline: 1.3700x; 1.3700x over previous
#include <cuda_runtime.h>
#include <cuda_bf16.h>
#include <cstddef>
#include <cstdint>

// Problem constants (fixed by the dataset)
#define BATCH 64
#define LSEQ  512
#define DIN   256
#define HDIM  256
#define H3    768
#define ADIM  128
#define DEPTH 4
#define NROWS (LSEQ * BATCH)   // 32768

#define CLUSTER_NCTAS 8
#define ROWS_PER_CTA  96       // 768 / 8
#define NBAT          4
#define NCLU          16
#define SCAN_THREADS  896
#define GOUT_F4       100      // 96 data float4 + 8 stats floats + pad
#define CLUBUF        (CLUSTER_NCTAS * GOUT_F4 * 4)   // 3200 floats per parity
#define SL_STRIDE     520      // steplist ints per batch (513 used)

// SMEM weight layout: row r = 72 float4 (8 kq-blocks of 9: 8 data + 1 pad)
#define WROW_F4  72
// hT layout: float4 per k (4 batches), 33-f4 blocks (32 data + 1 pad)
#define HT_F4(k)        ((((k) >> 5) * 33) + ((k) & 31))
#define HT_FLT(k, b)    ((((k) >> 5) * 132) + (((k) & 31) * 4) + (b))

// ---------------- scratch (device globals; no allocation allowed) -------------
__device__ float g_h0  [(size_t)NROWS * HDIM];
__device__ float g_h1  [(size_t)NROWS * HDIM];
__device__ float g_xpc [(size_t)(NROWS + 64) * H3];  // compacted xp
__device__ float g_xa  [(size_t)NROWS * ADIM];
__device__ float g_Ut  [(size_t)H3 * HDIM];          // U^T (768x256)
__device__ float g_hp  [(size_t)NCLU * 2 * CLUBUF];
__device__ int   g_steplist[BATCH * SL_STRIDE];
__device__ int   g_src  [BATCH * LSEQ];
__device__ int   g_nsteps[BATCH];
__device__ int   g_off  [BATCH + 1];
__device__ int   g_rowA [NROWS + 64];
__device__ int   g_mtotal;
__device__ unsigned char g_mask[BATCH * LSEQ];

// ---------------------------------- helpers ----------------------------------
__device__ __forceinline__ float warp_sum(float v) {
#pragma unroll
    for (int o = 16; o > 0; o >>= 1) v += __shfl_down_sync(0xffffffffu, v, o);
    return v;
}
// fast activations (err ~1e-6; saturate correctly at +/-inf)
__device__ __forceinline__ float fsig(float x) {
    float e = __expf(-x);
    return __fdividef(1.0f, 1.0f + e);
}
__device__ __forceinline__ float ftanhf(float x) {
    float e = __expf(2.0f * x);
    return 1.0f - __fdividef(2.0f, e + 1.0f);
}
__device__ __forceinline__ void fma2(unsigned long long& d, unsigned long long a,
                                     unsigned long long b) {
    asm("fma.rn.f32x2 %0, %1, %2, %0;" : "+l"(d) : "l"(a), "l"(b));
}
__device__ __forceinline__ unsigned long long pk(float lo, float hi) {
    unsigned long long r;
    asm("mov.b64 %0, {%1, %2};" : "=l"(r) : "f"(lo), "f"(hi));
    return r;
}
__device__ __forceinline__ float2 upk(unsigned long long v) {
    float2 r;
    asm("mov.b64 {%0, %1}, %2;" : "=f"(r.x), "=f"(r.y) : "l"(v));
    return r;
}
__device__ __forceinline__ float sum4(float4 v) { return (v.x + v.y) + (v.z + v.w); }
__device__ __forceinline__ float sq4(float4 v)  { return (v.x * v.x + v.y * v.y) + (v.z * v.z + v.w * v.w); }

// ----------------- prep: U transpose + mask copy + depth-0 plan ---------------
__global__ void prep_fused(const float* __restrict__ U,
                           const unsigned char* __restrict__ m8) {
    int k = blockIdx.x;
    if (k < H3) {
        int i = threadIdx.x;  // 0..255
        g_Ut[(size_t)k * HDIM + i] = U[(size_t)i * H3 + k];
        return;
    }
    __shared__ unsigned char smm[BATCH * LSEQ];
    __shared__ int mode;
    int t = threadIdx.x;
    if (t == 0) {
        int nz = 0;
        for (int i = 0; i < 64; i++) nz |= m8[4 * i + 1] | m8[4 * i + 2] | m8[4 * i + 3];
        mode = nz ? 1 : 0;
    }
    __syncthreads();
    if (mode) {
        for (int i = t; i < BATCH * LSEQ; i += blockDim.x) {
            unsigned char v = m8[i] ? 1 : 0;
            g_mask[i] = v; smm[i] = v;
        }
    } else {
        const int* m32 = (const int*)m8;
        for (int i = t; i < BATCH * LSEQ; i += blockDim.x) {
            unsigned char v = m32[i] ? 1 : 0;
            g_mask[i] = v; smm[i] = v;
        }
    }
    __syncthreads();
    if (t < BATCH) {
        int b = t, n = 0, src = -1;
        for (int l = 0; l < LSEQ; l++) {
            if (smm[b * LSEQ + l]) { g_steplist[b * SL_STRIDE + n] = l; n++; src = l; }
            else                   { g_src[b * LSEQ + l] = src; }
        }
        g_nsteps[b] = n;
        for (int i = n; i <= LSEQ; i++) g_steplist[b * SL_STRIDE + i] = -1;
    }
    __syncthreads();
    if (t == 0) {
        int acc = 0;
        for (int b = 0; b < BATCH; b++) { g_off[b] = acc; acc += g_nsteps[b]; }
        g_off[BATCH] = acc;
        g_mtotal = acc;
    }
    __syncthreads();
    if (t < BATCH) {
        int b = t, off = g_off[b], n = g_nsteps[b];
        for (int i = 0; i < n; i++)
            g_rowA[off + i] = g_steplist[b * SL_STRIDE + i] * BATCH + b;
    }
}

// ---------------- plan (d>=1): lists + src + offsets + rowlist (one block) ----
__global__ void plan_kernel() {
    __shared__ unsigned char smm[BATCH * LSEQ];
    int t = threadIdx.x;   // 1024
    for (int i = t; i < BATCH * LSEQ; i += blockDim.x) smm[i] = g_mask[i];
    __syncthreads();
    if (t < BATCH) {
        int b = t, n = 0, src = -1;
        for (int l = 0; l < LSEQ; l++) {
            if (smm[b * LSEQ + l]) { g_steplist[b * SL_STRIDE + n] = l; n++; src = l; }
            else                   { g_src[b * LSEQ + l] = src; }
        }
        g_nsteps[b] = n;
        for (int i = n; i <= LSEQ; i++) g_steplist[b * SL_STRIDE + i] = -1;
    }
    __syncthreads();
    if (t == 0) {
        int acc = 0;
        for (int b = 0; b < BATCH; b++) { g_off[b] = acc; acc += g_nsteps[b]; }
        g_off[BATCH] = acc;
        g_mtotal = acc;
    }
    __syncthreads();
    if (t < BATCH) {
        int b = t, off = g_off[b], n = g_nsteps[b];
        for (int i = 0; i < n; i++)
            g_rowA[off + i] = g_steplist[b * SL_STRIDE + i] * BATCH + b;
    }
}

// ------------------------------- tiled SGEMM (f32x2) --------------------------
// MODE 0: plain. MODE 1: A row r -> x[b=r&63][l=r>>6] (embed). MODE 2: A row
// r -> A row r-64 (zeros for r<64), C += result. MODE 3: A row r -> A row
// g_rowA[r] (compacted-mask gather; early-exit blocks beyond g_mtotal).
template <int MODE>
__global__ void __launch_bounds__(256) sgemm_kernel(
    const float* __restrict__ A, const float* __restrict__ Bm,
    const float* __restrict__ bias, float* __restrict__ C, int N) {
    const int K = 256;
    __shared__ __align__(16) float Ast[16][68];
    __shared__ __align__(16) float Bs[16][64];
    int t  = threadIdx.x;
    int m0 = blockIdx.y * 64;
    int n0 = blockIdx.x * 64;
    if (MODE == 3 && m0 >= g_mtotal) return;   // uniform per block
    int ty = t >> 4, tx = t & 15;

    unsigned long long acc2[4][2];
#pragma unroll
    for (int i = 0; i < 4; i++) { acc2[i][0] = 0ull; acc2[i][1] = 0ull; }

    int ar = t >> 2;
    int ak = (t & 3) * 4;
    int arow = m0 + ar;
    const float* Aptr;
    if (MODE == 1) {
        int b = arow & 63, l = arow >> 6;
        Aptr = A + ((size_t)b * LSEQ + l) * K;
    } else if (MODE == 2) {
        Aptr = A + (size_t)(arow - 64) * K;
    } else if (MODE == 3) {
        int mt = g_mtotal;
        int rr = (arow < mt) ? arow : (mt - 1);
        Aptr = A + (size_t)g_rowA[rr] * K;
    } else {
        Aptr = A + (size_t)arow * K;
    }
    const bool avalid = (MODE != 2) || (arow >= 64);
    int bk = t >> 4;
    int bn = (t & 15) * 4;

    for (int k0 = 0; k0 < K; k0 += 16) {
        float4 av = make_float4(0.f, 0.f, 0.f, 0.f);
        if (avalid) av = *(const float4*)(Aptr + k0 + ak);
        Ast[ak + 0][ar] = av.x;
        Ast[ak + 1][ar] = av.y;
        Ast[ak + 2][ar] = av.z;
        Ast[ak + 3][ar] = av.w;
        *(float4*)(&Bs[bk][bn]) = *(const float4*)(Bm + (size_t)(k0 + bk) * N + n0 + bn);
        __syncthreads();
#pragma unroll
        for (int kk = 0; kk < 16; kk++) {
            float4 a  = *(const float4*)(&Ast[kk][ty * 4]);
            float4 bb = *(const float4*)(&Bs[kk][tx * 4]);
            unsigned long long b01 = pk(bb.x, bb.y), b23 = pk(bb.z, bb.w);
            unsigned long long ax = pk(a.x, a.x), ay = pk(a.y, a.y);
            unsigned long long az = pk(a.z, a.z), aw = pk(a.w, a.w);
            fma2(acc2[0][0], ax, b01); fma2(acc2[0][1], ax, b23);
            fma2(acc2[1][0], ay, b01); fma2(acc2[1][1], ay, b23);
            fma2(acc2[2][0], az, b01); fma2(acc2[2][1], az, b23);
            fma2(acc2[3][0], aw, b01); fma2(acc2[3][1], aw, b23);
        }
        __syncthreads();
    }
#pragma unroll
    for (int i = 0; i < 4; i++) {
        int row = m0 + ty * 4 + i;
        float2 v01 = upk(acc2[i][0]), v23 = upk(acc2[i][1]);
        float4 v;
        v.x = v01.x; v.y = v01.y; v.z = v23.x; v.w = v23.y;
        if (MODE != 2 && bias) {
            v.x += bias[n0 + tx * 4 + 0];
            v.y += bias[n0 + tx * 4 + 1];
            v.z += bias[n0 + tx * 4 + 2];
            v.w += bias[n0 + tx * 4 + 3];
        }
        float4* cp = (float4*)(&C[(size_t)row * N + n0 + tx * 4]);
        if (MODE == 2) {
            float4 o = *cp;
            v.x += o.x; v.y += o.y; v.z += o.z; v.w += o.w;
        }
        *cp = v;
    }
}

// -------------------- fill: masked h_out rows = carried h ---------------------
__global__ void fill_kernel(float* __restrict__ hout) {
    int l = blockIdx.x, b = blockIdx.y, t = threadIdx.x;   // 64 threads
    if (g_mask[b * LSEQ + l]) return;
    int src = g_src[b * LSEQ + l];
    float4 v = make_float4(0.f, 0.f, 0.f, 0.f);
    if (src >= 0) v = ((const float4*)hout)[((size_t)src * BATCH + b) * 64 + t];
    ((float4*)hout)[((size_t)l * BATCH + b) * 64 + t] = v;
}

// -------------------- head: bulk action/policy + next mask --------------------
__global__ void head_kernel(int d, const float* __restrict__ lin,
                            const float* __restrict__ ba1,
                            const float* __restrict__ Wa2,
                            const float* __restrict__ ba2,
                            const float* __restrict__ hout,
                            float* __restrict__ out, int out_size) {
    int r = blockIdx.x;            // (l,b) row: r = l*64 + b
    int l = r >> 6, b = r & 63;
    int t = threadIdx.x;           // 128
    __shared__ float s[8];

    float v = tanhf(lin[(size_t)r * ADIM + t] + ba1[t]);
    float p0 = warp_sum(v * Wa2[2 * t]);
    float p1 = warp_sum(v * Wa2[2 * t + 1]);
    if ((t & 31) == 0) { s[(t >> 5) * 2] = p0; s[(t >> 5) * 2 + 1] = p1; }

    if (d == DEPTH - 1 && l == LSEQ - 1 && out_size >= BATCH * HDIM) {
        const float* hr = hout + ((size_t)(LSEQ - 1) * BATCH + b) * HDIM;
        out[b * HDIM + t]       = hr[t];
        out[b * HDIM + 128 + t] = hr[128 + t];
    }
    __syncthreads();
    if (t == 0) {
        float l0 = s[0] + s[2] + s[4] + s[6] + ba2[0];
        float l1 = s[1] + s[3] + s[5] + s[7] + ba2[1];
        unsigned char mt = g_mask[b * LSEQ + l];
        unsigned char act = ((l1 > l0) && mt) ? 1 : 0;
        g_mask[b * LSEQ + l] = act;      // next-depth mask
        if (out_size >= 409600) {
            float m = fmaxf(l0, l1);
            float e0 = expf(l0 - m), e1 = expf(l1 - m);
            float inv = 1.0f / (e0 + e1);
            size_t ai = (size_t)BATCH * HDIM + ((size_t)(b * DEPTH + d)) * LSEQ + l;
            out[ai] = act ? 1.0f : 0.0f;
            size_t pi = (size_t)BATCH * HDIM + (size_t)BATCH * DEPTH * LSEQ +
                        (((size_t)(b * DEPTH + d)) * LSEQ + l) * 2;
            out[pi]     = e0 * inv;
            out[pi + 1] = e1 * inv;
        }
    }
}

// --------------- cluster scan: recurrence only, compacted xp ------------------
// R9 protocol (best known): single cluster barrier/iter, L2 gout exchange,
// symmetric redundant phase B. xp now read from the compacted buffer: batch bb's
// it-th active step is row off[bb]+it (contiguous streaming).
__global__ void __cluster_dims__(CLUSTER_NCTAS, 1, 1) __launch_bounds__(SCAN_THREADS, 1)
scan8_kernel(const float* __restrict__ bg,
             const float* __restrict__ gammas,
             const float* __restrict__ betas,
             float* __restrict__ hout) {
    extern __shared__ __align__(16) float sm[];
    float* Wsm   = sm;                                // 27648
    float* s_hT  = Wsm  + ROWS_PER_CTA * WROW_F4 * 4; // 1056
    float* s_hp  = s_hT + 1056;                       // 768*5 = 3840
    float* s_xpa = s_hp + 768 * 5;                    // 2*4*768 = 6144
    float* c_g0  = s_xpa + 2 * NBAT * H3;             // 768
    float* c_b0  = c_g0 + H3;
    float* c_g1  = c_b0 + H3;
    float* c_b1  = c_g1 + H3;
    float* c_bg  = c_b1 + H3;
    float* s_lnA = c_bg + H3;                         // 192
    float* s_stat= s_lnA + 192;                       // 8
    float* s_xscr= s_stat + 8;                        // 32
    float* s_xst = s_xscr + 32;                       // 16
    int*   s_lb  = (int*)(s_xst + 16);                // 8
    int*   s_off = s_lb + 8;                          // 4
    int*   s_ns  = s_off + 4;                         // 4

    const int t    = threadIdx.x;
    const int rank = blockIdx.x & (CLUSTER_NCTAS - 1);
    const int clu  = blockIdx.x >> 3;
    const int b0   = clu * NBAT;
    const int lane = t & 31, wid = t >> 5;

    // ---- weight slice (rows 96*rank..+95 of U^T) into padded layout ----
    {
        const float4* src = (const float4*)(g_Ut + (size_t)(ROWS_PER_CTA * rank) * HDIM);
        float4* dst = (float4*)Wsm;
        for (int i = t; i < ROWS_PER_CTA * 64; i += SCAN_THREADS) {
            int row = i >> 6, c4 = i & 63;
            dst[row * WROW_F4 + (c4 >> 3) * 9 + (c4 & 7)] = src[(size_t)row * 64 + c4];
        }
    }
    for (int i = t; i < H3; i += SCAN_THREADS) {
        c_g0[i] = gammas[i];
        c_b0[i] = betas[i];
        c_g1[i] = gammas[H3 + i];
        c_b1[i] = betas[H3 + i];
        c_bg[i] = bg[i];
    }
    for (int i = t; i < 1056; i += SCAN_THREADS) s_hT[i] = 0.0f;

    int maxit = 0;
#pragma unroll
    for (int i = 0; i < 4; i++) {
        int n = g_nsteps[b0 + i];
        maxit = (n > maxit) ? n : maxit;
    }
    if (t < 4) {
        s_lb[t]  = g_steplist[(b0 + t) * SL_STRIDE];
        s_off[t] = g_off[b0 + t];
        s_ns[t]  = g_nsteps[b0 + t];
    }
    __syncthreads();

    // prologue: load xp(compact it=0) for active batches
    if (t < 768) {
        int bb = t / 192, c4 = t - 192 * bb;
        if (s_ns[bb] > 0)
            ((float4*)s_xpa)[bb * 192 + c4] =
                *((const float4*)g_xpc + (size_t)s_off[bb] * 192 + c4);
    }
    __syncthreads();
    if (t >= 768) {   // xp stats for it=0 (4 helper warps, one per batch)
        int u = t - 768, bb = u >> 5;
        const float* xr = s_xpa + bb * H3;
        float s = 0.f, q = 0.f;
#pragma unroll
        for (int j = 0; j < 24; j++) { float v = xr[(u & 31) + 32 * j]; s += v; q += v * v; }
        s = warp_sum(s); q = warp_sum(q);
        if ((u & 31) == 0) {
            float mu = s * (1.0f / 768.0f), var = q * (1.0f / 768.0f) - mu * mu;
            s_xst[bb] = mu; s_xst[4 + bb] = rsqrtf(var + 1e-5f);
        }
    }
    __syncthreads();

    const int r_ = t >> 3, kq = t & 7;
    const float4* wf = (const float4*)Wsm + r_ * WROW_F4 + kq * 9;
    const float4* ht = (const float4*)s_hT;
    float* gbase = g_hp + (size_t)clu * (2 * CLUBUF);

    for (int it = 0; it < maxit; ++it) {
        const int par = it & 1, nxt = par ^ 1;
        float* gout = gbase + par * CLUBUF;

        // ================ phase A ================
        float4 pf0, pf1, pf2, pf3, pf4, pf5;
        if (t < 768) {
            // plain-FFMA matvec: weights loaded once, 4 independent batch accs
            float d0 = 0.f, d1 = 0.f, d2 = 0.f, d3 = 0.f;
#pragma unroll
            for (int i = 0; i < 8; i++) {
                float4 w  = wf[i];
                float4 h0 = ht[kq * 33 + i * 4 + 0];
                float4 h1 = ht[kq * 33 + i * 4 + 1];
                float4 h2 = ht[kq * 33 + i * 4 + 2];
                float4 h3 = ht[kq * 33 + i * 4 + 3];
                d0 += w.x * h0.x; d1 += w.x * h0.y; d2 += w.x * h0.z; d3 += w.x * h0.w;
                d0 += w.y * h1.x; d1 += w.y * h1.y; d2 += w.y * h1.z; d3 += w.y * h1.w;
                d0 += w.z * h2.x; d1 += w.z * h2.y; d2 += w.z * h2.z; d3 += w.z * h2.w;
                d0 += w.w * h3.x; d1 += w.w * h3.y; d2 += w.w * h3.z; d3 += w.w * h3.w;
            }
#pragma unroll
            for (int m = 1; m < 8; m <<= 1) {
                d0 += __shfl_xor_sync(0xffffffffu, d0, m);
                d1 += __shfl_xor_sync(0xffffffffu, d1, m);
                d2 += __shfl_xor_sync(0xffffffffu, d2, m);
                d3 += __shfl_xor_sync(0xffffffffu, d3, m);
            }
            if (kq == 0) {
                float4 o; o.x = d0; o.y = d1; o.z = d2; o.w = d3;
                ((float4*)gout)[rank * GOUT_F4 + r_] = o;
            }
            float q0 = d0 * d0, q1 = d1 * d1, q2 = d2 * d2, q3 = d3 * d3;
#pragma unroll
            for (int m = 8; m <= 16; m <<= 1) {
                d0 += __shfl_xor_sync(0xffffffffu, d0, m);
                d1 += __shfl_xor_sync(0xffffffffu, d1, m);
                d2 += __shfl_xor_sync(0xffffffffu, d2, m);
                d3 += __shfl_xor_sync(0xffffffffu, d3, m);
                q0 += __shfl_xor_sync(0xffffffffu, q0, m);
                q1 += __shfl_xor_sync(0xffffffffu, q1, m);
                q2 += __shfl_xor_sync(0xffffffffu, q2, m);
                q3 += __shfl_xor_sync(0xffffffffu, q3, m);
            }
            if (lane == 0) {
                s_lnA[wid * 8 + 0] = d0; s_lnA[wid * 8 + 1] = d1;
                s_lnA[wid * 8 + 2] = d2; s_lnA[wid * 8 + 3] = d3;
                s_lnA[wid * 8 + 4] = q0; s_lnA[wid * 8 + 5] = q1;
                s_lnA[wid * 8 + 6] = q2; s_lnA[wid * 8 + 7] = q3;
            }
        } else {
            // helpers: next step indices + prefetch compacted xp(it+1)
            int u = t - 768;
            int lbv[4];
#pragma unroll
            for (int i = 0; i < 4; i++)
                lbv[i] = g_steplist[(b0 + i) * SL_STRIDE + it + 1];
            if (u < 4) s_lb[nxt * 4 + u] = lbv[u];
            const float4* xpf4 = (const float4*)g_xpc;
#pragma unroll
            for (int j = 0; j < 6; j++) {
                int idx = u + 128 * j;
                int bb = idx / 192, c4 = idx - 192 * bb;
                float4 vv = make_float4(0.f, 0.f, 0.f, 0.f);
                if (it + 1 < s_ns[bb])
                    vv = xpf4[(size_t)(s_off[bb] + it + 1) * 192 + c4];
                switch (j) {
                    case 0: pf0 = vv; break;
                    case 1: pf1 = vv; break;
                    case 2: pf2 = vv; break;
                    case 3: pf3 = vv; break;
                    case 4: pf4 = vv; break;
                    case 5: pf5 = vv; break;
                }
            }
        }
        __syncthreads();
        if (t < 8) {
            float acc = 0.f;
#pragma unroll
            for (int w = 0; w < 24; w++) acc += s_lnA[w * 8 + t];
            gout[rank * GOUT_F4 * 4 + 384 + t] = acc;
        }

        asm volatile("barrier.cluster.arrive.aligned;" ::: "memory");
        asm volatile("barrier.cluster.wait.aligned;" ::: "memory");

        // ============ gather phase: hp gather | LN stats | pf store+stats ======
        if (t < 768) {
            int rank_r = t / 96, wrow_r = t - 96 * rank_r;
            float4 v = __ldcv((const float4*)gout + rank_r * GOUT_F4 + wrow_r);
            float* dst = s_hp + t * 5;
            dst[0] = v.x; dst[1] = v.y; dst[2] = v.z; dst[3] = v.w;
            if (t < 4) {
                float S = 0.f, Q = 0.f;
#pragma unroll
                for (int r8 = 0; r8 < 8; r8++) {
                    S += __ldcv(gout + r8 * GOUT_F4 * 4 + 384 + t);
                    Q += __ldcv(gout + r8 * GOUT_F4 * 4 + 384 + 4 + t);
                }
                float mu  = S * (1.0f / 768.0f);
                float var = Q * (1.0f / 768.0f) - mu * mu;
                s_stat[t]     = mu;
                s_stat[4 + t] = rsqrtf(var + 1e-5f);
            }
        } else {
            int u = t - 768;
            float* xd = s_xpa + nxt * (NBAT * H3);
            ((float4*)xd)[u + 0]   = pf0;
            ((float4*)xd)[u + 128] = pf1;
            ((float4*)xd)[u + 256] = pf2;
            ((float4*)xd)[u + 384] = pf3;
            ((float4*)xd)[u + 512] = pf4;
            ((float4*)xd)[u + 640] = pf5;
            float xs0 = sum4(pf0), xq0 = sq4(pf0);
            float xs1 = sum4(pf2), xq1 = sq4(pf2);
            float xs2 = sum4(pf3), xq2 = sq4(pf3);
            float xs3 = sum4(pf5), xq3 = sq4(pf5);
            float s1v = sum4(pf1), q1v = sq4(pf1);
            float s4v = sum4(pf4), q4v = sq4(pf4);
            if (u < 64) { xs0 += s1v; xq0 += q1v; xs2 += s4v; xq2 += q4v; }
            else        { xs1 += s1v; xq1 += q1v; xs3 += s4v; xq3 += q4v; }
#pragma unroll
            for (int m = 1; m < 32; m <<= 1) {
                xs0 += __shfl_xor_sync(0xffffffffu, xs0, m);
                xs1 += __shfl_xor_sync(0xffffffffu, xs1, m);
                xs2 += __shfl_xor_sync(0xffffffffu, xs2, m);
                xs3 += __shfl_xor_sync(0xffffffffu, xs3, m);
                xq0 += __shfl_xor_sync(0xffffffffu, xq0, m);
                xq1 += __shfl_xor_sync(0xffffffffu, xq1, m);
                xq2 += __shfl_xor_sync(0xffffffffu, xq2, m);
                xq3 += __shfl_xor_sync(0xffffffffu, xq3, m);
            }
            if (lane == 0) {
                int w = wid - 24;
                s_xscr[w * 8 + 0] = xs0; s_xscr[w * 8 + 1] = xs1;
                s_xscr[w * 8 + 2] = xs2; s_xscr[w * 8 + 3] = xs3;
                s_xscr[w * 8 + 4] = xq0; s_xscr[w * 8 + 5] = xq1;
                s_xscr[w * 8 + 6] = xq2; s_xscr[w * 8 + 7] = xq3;
            }
        }
        __syncthreads();

        // ============ gates phase (t<512) | xst combine (4 helpers) ============
        if (t < 512) {
            int col = t & 255;
#pragma unroll
            for (int rep = 0; rep < 2; rep++) {
                int bb = (t >> 8) + rep * 2;
                int lb = s_lb[par * 4 + bb];
                if (lb >= 0) {
                    float mu = s_stat[bb], rs = s_stat[4 + bb];
                    float mux = s_xst[par * 8 + bb], rsx = s_xst[par * 8 + 4 + bb];
                    const float* xr = s_xpa + (par * NBAT + bb) * H3;
                    float x0 = c_g0[col]       * (xr[col]       - mux) * rsx + c_b0[col];
                    float x1 = c_g0[col + 256] * (xr[col + 256] - mux) * rsx + c_b0[col + 256];
                    float x2 = c_g0[col + 512] * (xr[col + 512] - mux) * rsx + c_b0[col + 512];
                    float hp0 = (s_hp[col * 5 + bb]         - mu) * rs * c_g1[col]       + c_b1[col];
                    float hp1 = (s_hp[(col + 256) * 5 + bb] - mu) * rs * c_g1[col + 256] + c_b1[col + 256];
                    float hp2 = (s_hp[(col + 512) * 5 + bb] - mu) * rs * c_g1[col + 512] + c_b1[col + 512];
                    float r  = fsig(x0 + hp0     + c_bg[col]);
                    float z  = fsig(x1 + hp1     + c_bg[col + 256]);
                    float hh = ftanhf(x2 + r * hp2 + c_bg[col + 512]);
                    float hold = s_hT[HT_FLT(col, bb)];
                    float ho = z * hold + (1.0f - z) * hh;
                    s_hT[HT_FLT(col, bb)] = ho;
                    if (rank == bb)
                        hout[((size_t)lb * BATCH + b0 + bb) * HDIM + col] = ho;
                }
            }
        } else if (t >= 768 && t < 772) {
            int bb = t - 768;
            float S = s_xscr[bb] + s_xscr[8 + bb] + s_xscr[16 + bb] + s_xscr[24 + bb];
            float Q = s_xscr[4 + bb] + s_xscr[12 + bb] + s_xscr[20 + bb] + s_xscr[28 + bb];
            float mu = S * (1.0f / 768.0f), var = Q * (1.0f / 768.0f) - mu * mu;
            s_xst[nxt * 8 + bb] = mu; s_xst[nxt * 8 + 4 + bb] = rsqrtf(var + 1e-5f);
        }
        __syncthreads();   // s_hT / s_lb / s_xpa / s_xst stable for next iter
    }
}

// --------------------------------- launcher ----------------------------------
extern "C" void kernel_launch(void* const* d_in, const int* in_sizes, int n_in,
                              void* d_out, int out_size) {
    const float* x     = (const float*)d_in[0];
    const unsigned char* mask = (const unsigned char*)d_in[1];
    const float* W_emb = (const float*)d_in[2];
    const float* b_emb = (const float*)d_in[3];
    const float* W     = (const float*)d_in[4];
    const float* U     = (const float*)d_in[5];
    const float* bgate = (const float*)d_in[6];
    const float* Wa1   = (const float*)d_in[7];
    const float* Ua1   = (const float*)d_in[8];
    const float* ba1   = (const float*)d_in[9];
    const float* Wa2   = (const float*)d_in[10];
    const float* ba2   = (const float*)d_in[11];
    const float* gammas = (const float*)d_in[12];
    const float* betas  = (const float*)d_in[13];
    float* out = (float*)d_out;

    float *h0, *h1, *xpc, *xa;
    cudaGetSymbolAddress((void**)&h0, g_h0);
    cudaGetSymbolAddress((void**)&h1, g_h1);
    cudaGetSymbolAddress((void**)&xpc, g_xpc);
    cudaGetSymbolAddress((void**)&xa, g_xa);

    const int scan_smem =
        (ROWS_PER_CTA * WROW_F4 * 4 + 1056 + 768 * 5 + 2 * NBAT * H3 +
         5 * H3 + 192 + 8 + 32 + 16 + 8 + 4 + 4) * 4;
    static int attr_done = 0;
    if (!attr_done) {
        cudaFuncSetAttribute(scan8_kernel, cudaFuncAttributeMaxDynamicSharedMemorySize, scan_smem);
        attr_done = 1;
    }

    // launch order: 0 prep, 1 embed, 2 gemm_xp(compact), 3 SCAN (profiled), ...
    prep_fused<<<H3 + 1, HDIM>>>(U, mask);
    sgemm_kernel<1><<<dim3(HDIM / 64, NROWS / 64), 256>>>(x, W_emb, b_emb, h0, HDIM);

    for (int d = 0; d < DEPTH; d++) {
        float* hin  = (d & 1) ? h1 : h0;
        float* hout = (d & 1) ? h0 : h1;
        // compacted xp GEMM: only unmasked rows (early-exit blocks beyond mtotal)
        sgemm_kernel<3><<<dim3(H3 / 64, NROWS / 64), 256>>>(hin, W, nullptr, xpc, H3);
        scan8_kernel<<<NCLU * CLUSTER_NCTAS, SCAN_THREADS, scan_smem>>>(
            bgate, gammas, betas, hout);
        sgemm_kernel<0><<<dim3(ADIM / 64, NROWS / 64), 256>>>(hin, Wa1, nullptr, xa, ADIM);
        fill_kernel<<<dim3(LSEQ, BATCH), 64>>>(hout);
        sgemm_kernel<2><<<dim3(ADIM / 64, NROWS / 64), 256>>>(hout, Ua1, nullptr, xa, ADIM);
        head_kernel<<<NROWS, 128>>>(d, xa, ba1, Wa2, ba2, hout, out, out_size);
        if (d < DEPTH - 1) plan_kernel<<<1, 1024>>>();
    }
}

// round 12
// speedup vs baseline: 1.3879x; 1.0130x over previous
#include <cuda_runtime.h>
#include <cuda_bf16.h>
#include <cstddef>
#include <cstdint>

// Problem constants (fixed by the dataset)
#define BATCH 64
#define LSEQ  512
#define DIN   256
#define HDIM  256
#define H3    768
#define ADIM  128
#define DEPTH 4
#define NROWS (LSEQ * BATCH)   // 32768

#define CLUSTER_NCTAS 8
#define ROWS_PER_CTA  96       // 768 / 8
#define NBAT          4
#define NCLU          16
#define SCAN_THREADS  896
#define GOUT_F4       100      // 96 data float4 + 8 stats floats + pad
#define CLUBUF        (CLUSTER_NCTAS * GOUT_F4 * 4)   // 3200 floats per parity
#define SL_STRIDE     520      // steplist ints per batch (513 used)

// SMEM weight layout: row r = 72 float4 (8 kq-blocks of 9: 8 data + 1 pad)
#define WROW_F4  72
// hT layout: float4 per k (4 batches), 33-f4 blocks (32 data + 1 pad)
#define HT_F4(k)        ((((k) >> 5) * 33) + ((k) & 31))
#define HT_FLT(k, b)    ((((k) >> 5) * 132) + (((k) & 31) * 4) + (b))

// ---------------- scratch (device globals; no allocation allowed) -------------
__device__ float g_h0  [(size_t)NROWS * HDIM];
__device__ float g_h1  [(size_t)NROWS * HDIM];
__device__ float g_xpc [(size_t)(NROWS + 64) * H3];  // compacted xp
__device__ float g_xa  [(size_t)NROWS * ADIM];
__device__ float g_Ut  [(size_t)H3 * HDIM];          // U^T (768x256)
__device__ float g_hp  [(size_t)NCLU * 2 * CLUBUF];
__device__ int   g_steplist[BATCH * SL_STRIDE];
__device__ int   g_nsteps[BATCH];
__device__ int   g_off  [BATCH + 1];
__device__ int   g_rowA [NROWS + 64];
__device__ int   g_srcE [NROWS];       // row idx of h before step l (or -1)
__device__ int   g_srcI [2][NROWS];    // row idx of h_full at step l (ping-pong)
__device__ int   g_mtotal;
__device__ unsigned char g_mask[BATCH * LSEQ];

// ---------------------------------- helpers ----------------------------------
__device__ __forceinline__ float warp_sum(float v) {
#pragma unroll
    for (int o = 16; o > 0; o >>= 1) v += __shfl_down_sync(0xffffffffu, v, o);
    return v;
}
// fast activations (err ~1e-6; saturate correctly at +/-inf)
__device__ __forceinline__ float fsig(float x) {
    float e = __expf(-x);
    return __fdividef(1.0f, 1.0f + e);
}
__device__ __forceinline__ float ftanhf(float x) {
    float e = __expf(2.0f * x);
    return 1.0f - __fdividef(2.0f, e + 1.0f);
}
__device__ __forceinline__ void fma2(unsigned long long& d, unsigned long long a,
                                     unsigned long long b) {
    asm("fma.rn.f32x2 %0, %1, %2, %0;" : "+l"(d) : "l"(a), "l"(b));
}
__device__ __forceinline__ unsigned long long pk(float lo, float hi) {
    unsigned long long r;
    asm("mov.b64 %0, {%1, %2};" : "=l"(r) : "f"(lo), "f"(hi));
    return r;
}
__device__ __forceinline__ float2 upk(unsigned long long v) {
    float2 r;
    asm("mov.b64 {%0, %1}, %2;" : "=f"(r.x), "=f"(r.y) : "l"(v));
    return r;
}
__device__ __forceinline__ float sum4(float4 v) { return (v.x + v.y) + (v.z + v.w); }
__device__ __forceinline__ float sq4(float4 v)  { return (v.x * v.x + v.y * v.y) + (v.z * v.z + v.w * v.w); }

// ------------- per-batch plan body (lists, offsets, rowA, srcE, srcI) ---------
__device__ __forceinline__ void plan_batch(const unsigned char* m, int b, int ibuf) {
    int n = 0, src = -1;
    for (int l = 0; l < LSEQ; l++) {
        int prev = src;
        if (m[l]) { g_steplist[b * SL_STRIDE + n] = l; n++; src = l; }
        int r = l * BATCH + b;
        g_srcE[r]       = (prev < 0) ? -1 : prev * BATCH + b;
        g_srcI[ibuf][r] = (src  < 0) ? -1 : src  * BATCH + b;
    }
    g_nsteps[b] = n;
    for (int i = n; i <= LSEQ; i++) g_steplist[b * SL_STRIDE + i] = -1;
}

// ----------------- prep: U transpose + mask copy + depth-0 plan ---------------
__global__ void prep_fused(const float* __restrict__ U,
                           const unsigned char* __restrict__ m8) {
    int k = blockIdx.x;
    if (k < H3) {
        int i = threadIdx.x;  // 0..255
        g_Ut[(size_t)k * HDIM + i] = U[(size_t)i * H3 + k];
        return;
    }
    __shared__ unsigned char smm[BATCH * LSEQ];
    __shared__ int mode;
    int t = threadIdx.x;
    if (t == 0) {
        int nz = 0;
        for (int i = 0; i < 64; i++) nz |= m8[4 * i + 1] | m8[4 * i + 2] | m8[4 * i + 3];
        mode = nz ? 1 : 0;
    }
    __syncthreads();
    if (mode) {
        for (int i = t; i < BATCH * LSEQ; i += blockDim.x) {
            unsigned char v = m8[i] ? 1 : 0;
            g_mask[i] = v; smm[i] = v;
        }
    } else {
        const int* m32 = (const int*)m8;
        for (int i = t; i < BATCH * LSEQ; i += blockDim.x) {
            unsigned char v = m32[i] ? 1 : 0;
            g_mask[i] = v; smm[i] = v;
        }
    }
    __syncthreads();
    if (t < BATCH) plan_batch(smm + t * LSEQ, t, 0);
    __syncthreads();
    if (t == 0) {
        int acc = 0;
        for (int b = 0; b < BATCH; b++) { g_off[b] = acc; acc += g_nsteps[b]; }
        g_off[BATCH] = acc;
        g_mtotal = acc;
    }
    __syncthreads();
    if (t < BATCH) {
        int b = t, off = g_off[b], n = g_nsteps[b];
        for (int i = 0; i < n; i++)
            g_rowA[off + i] = g_steplist[b * SL_STRIDE + i] * BATCH + b;
    }
}

// ---------------- plan (d>=1): one block, everything ---------------------------
__global__ void plan_kernel(int ibuf) {
    __shared__ unsigned char smm[BATCH * LSEQ];
    int t = threadIdx.x;   // 1024
    for (int i = t; i < BATCH * LSEQ; i += blockDim.x) smm[i] = g_mask[i];
    __syncthreads();
    if (t < BATCH) plan_batch(smm + t * LSEQ, t, ibuf);
    __syncthreads();
    if (t == 0) {
        int acc = 0;
        for (int b = 0; b < BATCH; b++) { g_off[b] = acc; acc += g_nsteps[b]; }
        g_off[BATCH] = acc;
        g_mtotal = acc;
    }
    __syncthreads();
    if (t < BATCH) {
        int b = t, off = g_off[b], n = g_nsteps[b];
        for (int i = 0; i < n; i++)
            g_rowA[off + i] = g_steplist[b * SL_STRIDE + i] * BATCH + b;
    }
}

// ------------------------------- tiled SGEMM (f32x2) --------------------------
// MODE 1: A row r -> x[b=r&63][l=r>>6] (embed). MODE 3: A row r -> A row
// g_rowA[r] (compacted-mask gather; early-exit blocks beyond g_mtotal).
template <int MODE>
__global__ void __launch_bounds__(256) sgemm_kernel(
    const float* __restrict__ A, const float* __restrict__ Bm,
    const float* __restrict__ bias, float* __restrict__ C, int N) {
    const int K = 256;
    __shared__ __align__(16) float Ast[16][68];
    __shared__ __align__(16) float Bs[16][64];
    int t  = threadIdx.x;
    int m0 = blockIdx.y * 64;
    int n0 = blockIdx.x * 64;
    if (MODE == 3 && m0 >= g_mtotal) return;   // uniform per block
    int ty = t >> 4, tx = t & 15;

    unsigned long long acc2[4][2];
#pragma unroll
    for (int i = 0; i < 4; i++) { acc2[i][0] = 0ull; acc2[i][1] = 0ull; }

    int ar = t >> 2;
    int ak = (t & 3) * 4;
    int arow = m0 + ar;
    const float* Aptr;
    if (MODE == 1) {
        int b = arow & 63, l = arow >> 6;
        Aptr = A + ((size_t)b * LSEQ + l) * K;
    } else {   // MODE 3
        int mt = g_mtotal;
        int rr = (arow < mt) ? arow : (mt - 1);
        Aptr = A + (size_t)g_rowA[rr] * K;
    }
    int bk = t >> 4;
    int bn = (t & 15) * 4;

    for (int k0 = 0; k0 < K; k0 += 16) {
        float4 av = *(const float4*)(Aptr + k0 + ak);
        Ast[ak + 0][ar] = av.x;
        Ast[ak + 1][ar] = av.y;
        Ast[ak + 2][ar] = av.z;
        Ast[ak + 3][ar] = av.w;
        *(float4*)(&Bs[bk][bn]) = *(const float4*)(Bm + (size_t)(k0 + bk) * N + n0 + bn);
        __syncthreads();
#pragma unroll
        for (int kk = 0; kk < 16; kk++) {
            float4 a  = *(const float4*)(&Ast[kk][ty * 4]);
            float4 bb = *(const float4*)(&Bs[kk][tx * 4]);
            unsigned long long b01 = pk(bb.x, bb.y), b23 = pk(bb.z, bb.w);
            unsigned long long ax = pk(a.x, a.x), ay = pk(a.y, a.y);
            unsigned long long az = pk(a.z, a.z), aw = pk(a.w, a.w);
            fma2(acc2[0][0], ax, b01); fma2(acc2[0][1], ax, b23);
            fma2(acc2[1][0], ay, b01); fma2(acc2[1][1], ay, b23);
            fma2(acc2[2][0], az, b01); fma2(acc2[2][1], az, b23);
            fma2(acc2[3][0], aw, b01); fma2(acc2[3][1], aw, b23);
        }
        __syncthreads();
    }
#pragma unroll
    for (int i = 0; i < 4; i++) {
        int row = m0 + ty * 4 + i;
        float2 v01 = upk(acc2[i][0]), v23 = upk(acc2[i][1]);
        float4 v;
        v.x = v01.x; v.y = v01.y; v.z = v23.x; v.w = v23.y;
        if (bias) {
            v.x += bias[n0 + tx * 4 + 0];
            v.y += bias[n0 + tx * 4 + 1];
            v.z += bias[n0 + tx * 4 + 2];
            v.w += bias[n0 + tx * 4 + 3];
        }
        *(float4*)(&C[(size_t)row * N + n0 + tx * 4]) = v;
    }
}

// -------- head GEMM: xa = hA[srcI]@Wa1 + hB[srcE]@Ua1 (K=512 fused gather) ----
__global__ void __launch_bounds__(256) gemm_head(
    const float* __restrict__ hA, const float* __restrict__ hB,
    const int* __restrict__ srcI,      // null => identity
    const float* __restrict__ Wa1, const float* __restrict__ Ua1,
    float* __restrict__ xa) {
    const int K = 256, N = ADIM;
    __shared__ __align__(16) float Ast[16][68];
    __shared__ __align__(16) float Bs[16][64];
    int t  = threadIdx.x;
    int m0 = blockIdx.y * 64;
    int n0 = blockIdx.x * 64;
    int ty = t >> 4, tx = t & 15;

    unsigned long long acc2[4][2];
#pragma unroll
    for (int i = 0; i < 4; i++) { acc2[i][0] = 0ull; acc2[i][1] = 0ull; }

    int ar = t >> 2;
    int ak = (t & 3) * 4;
    int arow = m0 + ar;
    int si = srcI ? srcI[arow] : arow;
    int se = g_srcE[arow];
    const float* pA = hA + (size_t)((si < 0) ? 0 : si) * K;
    const float* pB = hB + (size_t)((se < 0) ? 0 : se) * K;
    int bk = t >> 4;
    int bn = (t & 15) * 4;

#pragma unroll
    for (int pass = 0; pass < 2; pass++) {
        const float* Ap = (pass == 0) ? pA : pB;
        const bool valid = (pass == 0) ? (si >= 0) : (se >= 0);
        const float* Bp = (pass == 0) ? Wa1 : Ua1;
        for (int k0 = 0; k0 < K; k0 += 16) {
            float4 av = make_float4(0.f, 0.f, 0.f, 0.f);
            if (valid) av = *(const float4*)(Ap + k0 + ak);
            Ast[ak + 0][ar] = av.x;
            Ast[ak + 1][ar] = av.y;
            Ast[ak + 2][ar] = av.z;
            Ast[ak + 3][ar] = av.w;
            *(float4*)(&Bs[bk][bn]) = *(const float4*)(Bp + (size_t)(k0 + bk) * N + n0 + bn);
            __syncthreads();
#pragma unroll
            for (int kk = 0; kk < 16; kk++) {
                float4 a  = *(const float4*)(&Ast[kk][ty * 4]);
                float4 bb = *(const float4*)(&Bs[kk][tx * 4]);
                unsigned long long b01 = pk(bb.x, bb.y), b23 = pk(bb.z, bb.w);
                unsigned long long ax = pk(a.x, a.x), ay = pk(a.y, a.y);
                unsigned long long az = pk(a.z, a.z), aw = pk(a.w, a.w);
                fma2(acc2[0][0], ax, b01); fma2(acc2[0][1], ax, b23);
                fma2(acc2[1][0], ay, b01); fma2(acc2[1][1], ay, b23);
                fma2(acc2[2][0], az, b01); fma2(acc2[2][1], az, b23);
                fma2(acc2[3][0], aw, b01); fma2(acc2[3][1], aw, b23);
            }
            __syncthreads();
        }
    }
#pragma unroll
    for (int i = 0; i < 4; i++) {
        int row = m0 + ty * 4 + i;
        float2 v01 = upk(acc2[i][0]), v23 = upk(acc2[i][1]);
        float4 v;
        v.x = v01.x; v.y = v01.y; v.z = v23.x; v.w = v23.y;
        *(float4*)(&xa[(size_t)row * N + n0 + tx * 4]) = v;
    }
}

// -------------------- head: bulk action/policy + next mask --------------------
__global__ void head_kernel(int d, const float* __restrict__ lin,
                            const float* __restrict__ ba1,
                            const float* __restrict__ Wa2,
                            const float* __restrict__ ba2,
                            const float* __restrict__ hout,
                            float* __restrict__ out, int out_size) {
    int r = blockIdx.x;            // (l,b) row: r = l*64 + b
    int l = r >> 6, b = r & 63;
    int t = threadIdx.x;           // 128
    __shared__ float s[8];

    float v = tanhf(lin[(size_t)r * ADIM + t] + ba1[t]);
    float p0 = warp_sum(v * Wa2[2 * t]);
    float p1 = warp_sum(v * Wa2[2 * t + 1]);
    if ((t & 31) == 0) { s[(t >> 5) * 2] = p0; s[(t >> 5) * 2 + 1] = p1; }

    if (d == DEPTH - 1 && l == LSEQ - 1 && out_size >= BATCH * HDIM) {
        int n = g_nsteps[b];
        int last = (n > 0) ? g_steplist[b * SL_STRIDE + n - 1] : -1;
        if (last >= 0) {
            const float* hr = hout + ((size_t)last * BATCH + b) * HDIM;
            out[b * HDIM + t]       = hr[t];
            out[b * HDIM + 128 + t] = hr[128 + t];
        } else {
            out[b * HDIM + t]       = 0.0f;
            out[b * HDIM + 128 + t] = 0.0f;
        }
    }
    __syncthreads();
    if (t == 0) {
        float l0 = s[0] + s[2] + s[4] + s[6] + ba2[0];
        float l1 = s[1] + s[3] + s[5] + s[7] + ba2[1];
        unsigned char mt = g_mask[b * LSEQ + l];
        unsigned char act = ((l1 > l0) && mt) ? 1 : 0;
        g_mask[b * LSEQ + l] = act;      // next-depth mask
        if (out_size >= 409600) {
            float m = fmaxf(l0, l1);
            float e0 = expf(l0 - m), e1 = expf(l1 - m);
            float inv = 1.0f / (e0 + e1);
            size_t ai = (size_t)BATCH * HDIM + ((size_t)(b * DEPTH + d)) * LSEQ + l;
            out[ai] = act ? 1.0f : 0.0f;
            size_t pi = (size_t)BATCH * HDIM + (size_t)BATCH * DEPTH * LSEQ +
                        (((size_t)(b * DEPTH + d)) * LSEQ + l) * 2;
            out[pi]     = e0 * inv;
            out[pi + 1] = e1 * inv;
        }
    }
}

// --------------- cluster scan: recurrence only, compacted xp ------------------
// (R11 protocol, unchanged: single cluster barrier/iter, L2 gout exchange,
// symmetric redundant phase B, compacted contiguous xp streaming.)
__global__ void __cluster_dims__(CLUSTER_NCTAS, 1, 1) __launch_bounds__(SCAN_THREADS, 1)
scan8_kernel(const float* __restrict__ bg,
             const float* __restrict__ gammas,
             const float* __restrict__ betas,
             float* __restrict__ hout) {
    extern __shared__ __align__(16) float sm[];
    float* Wsm   = sm;                                // 27648
    float* s_hT  = Wsm  + ROWS_PER_CTA * WROW_F4 * 4; // 1056
    float* s_hp  = s_hT + 1056;                       // 768*5 = 3840
    float* s_xpa = s_hp + 768 * 5;                    // 2*4*768 = 6144
    float* c_g0  = s_xpa + 2 * NBAT * H3;             // 768
    float* c_b0  = c_g0 + H3;
    float* c_g1  = c_b0 + H3;
    float* c_b1  = c_g1 + H3;
    float* c_bg  = c_b1 + H3;
    float* s_lnA = c_bg + H3;                         // 192
    float* s_stat= s_lnA + 192;                       // 8
    float* s_xscr= s_stat + 8;                        // 32
    float* s_xst = s_xscr + 32;                       // 16
    int*   s_lb  = (int*)(s_xst + 16);                // 8
    int*   s_off = s_lb + 8;                          // 4
    int*   s_ns  = s_off + 4;                         // 4

    const int t    = threadIdx.x;
    const int rank = blockIdx.x & (CLUSTER_NCTAS - 1);
    const int clu  = blockIdx.x >> 3;
    const int b0   = clu * NBAT;
    const int lane = t & 31, wid = t >> 5;

    {
        const float4* src = (const float4*)(g_Ut + (size_t)(ROWS_PER_CTA * rank) * HDIM);
        float4* dst = (float4*)Wsm;
        for (int i = t; i < ROWS_PER_CTA * 64; i += SCAN_THREADS) {
            int row = i >> 6, c4 = i & 63;
            dst[row * WROW_F4 + (c4 >> 3) * 9 + (c4 & 7)] = src[(size_t)row * 64 + c4];
        }
    }
    for (int i = t; i < H3; i += SCAN_THREADS) {
        c_g0[i] = gammas[i];
        c_b0[i] = betas[i];
        c_g1[i] = gammas[H3 + i];
        c_b1[i] = betas[H3 + i];
        c_bg[i] = bg[i];
    }
    for (int i = t; i < 1056; i += SCAN_THREADS) s_hT[i] = 0.0f;

    int maxit = 0;
#pragma unroll
    for (int i = 0; i < 4; i++) {
        int n = g_nsteps[b0 + i];
        maxit = (n > maxit) ? n : maxit;
    }
    if (t < 4) {
        s_lb[t]  = g_steplist[(b0 + t) * SL_STRIDE];
        s_off[t] = g_off[b0 + t];
        s_ns[t]  = g_nsteps[b0 + t];
    }
    __syncthreads();

    if (t < 768) {
        int bb = t / 192, c4 = t - 192 * bb;
        if (s_ns[bb] > 0)
            ((float4*)s_xpa)[bb * 192 + c4] =
                *((const float4*)g_xpc + (size_t)s_off[bb] * 192 + c4);
    }
    __syncthreads();
    if (t >= 768) {
        int u = t - 768, bb = u >> 5;
        const float* xr = s_xpa + bb * H3;
        float s = 0.f, q = 0.f;
#pragma unroll
        for (int j = 0; j < 24; j++) { float v = xr[(u & 31) + 32 * j]; s += v; q += v * v; }
        s = warp_sum(s); q = warp_sum(q);
        if ((u & 31) == 0) {
            float mu = s * (1.0f / 768.0f), var = q * (1.0f / 768.0f) - mu * mu;
            s_xst[bb] = mu; s_xst[4 + bb] = rsqrtf(var + 1e-5f);
        }
    }
    __syncthreads();

    const int r_ = t >> 3, kq = t & 7;
    const float4* wf = (const float4*)Wsm + r_ * WROW_F4 + kq * 9;
    const float4* ht = (const float4*)s_hT;
    float* gbase = g_hp + (size_t)clu * (2 * CLUBUF);

    for (int it = 0; it < maxit; ++it) {
        const int par = it & 1, nxt = par ^ 1;
        float* gout = gbase + par * CLUBUF;

        // ================ phase A ================
        float4 pf0, pf1, pf2, pf3, pf4, pf5;
        if (t < 768) {
            float d0 = 0.f, d1 = 0.f, d2 = 0.f, d3 = 0.f;
#pragma unroll
            for (int i = 0; i < 8; i++) {
                float4 w  = wf[i];
                float4 h0 = ht[kq * 33 + i * 4 + 0];
                float4 h1 = ht[kq * 33 + i * 4 + 1];
                float4 h2 = ht[kq * 33 + i * 4 + 2];
                float4 h3 = ht[kq * 33 + i * 4 + 3];
                d0 += w.x * h0.x; d1 += w.x * h0.y; d2 += w.x * h0.z; d3 += w.x * h0.w;
                d0 += w.y * h1.x; d1 += w.y * h1.y; d2 += w.y * h1.z; d3 += w.y * h1.w;
                d0 += w.z * h2.x; d1 += w.z * h2.y; d2 += w.z * h2.z; d3 += w.z * h2.w;
                d0 += w.w * h3.x; d1 += w.w * h3.y; d2 += w.w * h3.z; d3 += w.w * h3.w;
            }
#pragma unroll
            for (int m = 1; m < 8; m <<= 1) {
                d0 += __shfl_xor_sync(0xffffffffu, d0, m);
                d1 += __shfl_xor_sync(0xffffffffu, d1, m);
                d2 += __shfl_xor_sync(0xffffffffu, d2, m);
                d3 += __shfl_xor_sync(0xffffffffu, d3, m);
            }
            if (kq == 0) {
                float4 o; o.x = d0; o.y = d1; o.z = d2; o.w = d3;
                ((float4*)gout)[rank * GOUT_F4 + r_] = o;
            }
            float q0 = d0 * d0, q1 = d1 * d1, q2 = d2 * d2, q3 = d3 * d3;
#pragma unroll
            for (int m = 8; m <= 16; m <<= 1) {
                d0 += __shfl_xor_sync(0xffffffffu, d0, m);
                d1 += __shfl_xor_sync(0xffffffffu, d1, m);
                d2 += __shfl_xor_sync(0xffffffffu, d2, m);
                d3 += __shfl_xor_sync(0xffffffffu, d3, m);
                q0 += __shfl_xor_sync(0xffffffffu, q0, m);
                q1 += __shfl_xor_sync(0xffffffffu, q1, m);
                q2 += __shfl_xor_sync(0xffffffffu, q2, m);
                q3 += __shfl_xor_sync(0xffffffffu, q3, m);
            }
            if (lane == 0) {
                s_lnA[wid * 8 + 0] = d0; s_lnA[wid * 8 + 1] = d1;
                s_lnA[wid * 8 + 2] = d2; s_lnA[wid * 8 + 3] = d3;
                s_lnA[wid * 8 + 4] = q0; s_lnA[wid * 8 + 5] = q1;
                s_lnA[wid * 8 + 6] = q2; s_lnA[wid * 8 + 7] = q3;
            }
        } else {
            int u = t - 768;
            int lbv[4];
#pragma unroll
            for (int i = 0; i < 4; i++)
                lbv[i] = g_steplist[(b0 + i) * SL_STRIDE + it + 1];
            if (u < 4) s_lb[nxt * 4 + u] = lbv[u];
            const float4* xpf4 = (const float4*)g_xpc;
#pragma unroll
            for (int j = 0; j < 6; j++) {
                int idx = u + 128 * j;
                int bb = idx / 192, c4 = idx - 192 * bb;
                float4 vv = make_float4(0.f, 0.f, 0.f, 0.f);
                if (it + 1 < s_ns[bb])
                    vv = xpf4[(size_t)(s_off[bb] + it + 1) * 192 + c4];
                switch (j) {
                    case 0: pf0 = vv; break;
                    case 1: pf1 = vv; break;
                    case 2: pf2 = vv; break;
                    case 3: pf3 = vv; break;
                    case 4: pf4 = vv; break;
                    case 5: pf5 = vv; break;
                }
            }
        }
        __syncthreads();
        if (t < 8) {
            float acc = 0.f;
#pragma unroll
            for (int w = 0; w < 24; w++) acc += s_lnA[w * 8 + t];
            gout[rank * GOUT_F4 * 4 + 384 + t] = acc;
        }

        asm volatile("barrier.cluster.arrive.aligned;" ::: "memory");
        asm volatile("barrier.cluster.wait.aligned;" ::: "memory");

        // ============ gather phase ============
        if (t < 768) {
            int rank_r = t / 96, wrow_r = t - 96 * rank_r;
            float4 v = __ldcv((const float4*)gout + rank_r * GOUT_F4 + wrow_r);
            float* dst = s_hp + t * 5;
            dst[0] = v.x; dst[1] = v.y; dst[2] = v.z; dst[3] = v.w;
            if (t < 4) {
                float S = 0.f, Q = 0.f;
#pragma unroll
                for (int r8 = 0; r8 < 8; r8++) {
                    S += __ldcv(gout + r8 * GOUT_F4 * 4 + 384 + t);
                    Q += __ldcv(gout + r8 * GOUT_F4 * 4 + 384 + 4 + t);
                }
                float mu  = S * (1.0f / 768.0f);
                float var = Q * (1.0f / 768.0f) - mu * mu;
                s_stat[t]     = mu;
                s_stat[4 + t] = rsqrtf(var + 1e-5f);
            }
        } else {
            int u = t - 768;
            float* xd = s_xpa + nxt * (NBAT * H3);
            ((float4*)xd)[u + 0]   = pf0;
            ((float4*)xd)[u + 128] = pf1;
            ((float4*)xd)[u + 256] = pf2;
            ((float4*)xd)[u + 384] = pf3;
            ((float4*)xd)[u + 512] = pf4;
            ((float4*)xd)[u + 640] = pf5;
            float xs0 = sum4(pf0), xq0 = sq4(pf0);
            float xs1 = sum4(pf2), xq1 = sq4(pf2);
            float xs2 = sum4(pf3), xq2 = sq4(pf3);
            float xs3 = sum4(pf5), xq3 = sq4(pf5);
            float s1v = sum4(pf1), q1v = sq4(pf1);
            float s4v = sum4(pf4), q4v = sq4(pf4);
            if (u < 64) { xs0 += s1v; xq0 += q1v; xs2 += s4v; xq2 += q4v; }
            else        { xs1 += s1v; xq1 += q1v; xs3 += s4v; xq3 += q4v; }
#pragma unroll
            for (int m = 1; m < 32; m <<= 1) {
                xs0 += __shfl_xor_sync(0xffffffffu, xs0, m);
                xs1 += __shfl_xor_sync(0xffffffffu, xs1, m);
                xs2 += __shfl_xor_sync(0xffffffffu, xs2, m);
                xs3 += __shfl_xor_sync(0xffffffffu, xs3, m);
                xq0 += __shfl_xor_sync(0xffffffffu, xq0, m);
                xq1 += __shfl_xor_sync(0xffffffffu, xq1, m);
                xq2 += __shfl_xor_sync(0xffffffffu, xq2, m);
                xq3 += __shfl_xor_sync(0xffffffffu, xq3, m);
            }
            if (lane == 0) {
                int w = wid - 24;
                s_xscr[w * 8 + 0] = xs0; s_xscr[w * 8 + 1] = xs1;
                s_xscr[w * 8 + 2] = xs2; s_xscr[w * 8 + 3] = xs3;
                s_xscr[w * 8 + 4] = xq0; s_xscr[w * 8 + 5] = xq1;
                s_xscr[w * 8 + 6] = xq2; s_xscr[w * 8 + 7] = xq3;
            }
        }
        __syncthreads();

        // ============ gates phase (t<512) | xst combine (4 helpers) ============
        if (t < 512) {
            int col = t & 255;
#pragma unroll
            for (int rep = 0; rep < 2; rep++) {
                int bb = (t >> 8) + rep * 2;
                int lb = s_lb[par * 4 + bb];
                if (lb >= 0) {
                    float mu = s_stat[bb], rs = s_stat[4 + bb];
                    float mux = s_xst[par * 8 + bb], rsx = s_xst[par * 8 + 4 + bb];
                    const float* xr = s_xpa + (par * NBAT + bb) * H3;
                    float x0 = c_g0[col]       * (xr[col]       - mux) * rsx + c_b0[col];
                    float x1 = c_g0[col + 256] * (xr[col + 256] - mux) * rsx + c_b0[col + 256];
                    float x2 = c_g0[col + 512] * (xr[col + 512] - mux) * rsx + c_b0[col + 512];
                    float hp0 = (s_hp[col * 5 + bb]         - mu) * rs * c_g1[col]       + c_b1[col];
                    float hp1 = (s_hp[(col + 256) * 5 + bb] - mu) * rs * c_g1[col + 256] + c_b1[col + 256];
                    float hp2 = (s_hp[(col + 512) * 5 + bb] - mu) * rs * c_g1[col + 512] + c_b1[col + 512];
                    float r  = fsig(x0 + hp0     + c_bg[col]);
                    float z  = fsig(x1 + hp1     + c_bg[col + 256]);
                    float hh = ftanhf(x2 + r * hp2 + c_bg[col + 512]);
                    float hold = s_hT[HT_FLT(col, bb)];
                    float ho = z * hold + (1.0f - z) * hh;
                    s_hT[HT_FLT(col, bb)] = ho;
                    if (rank == bb)
                        hout[((size_t)lb * BATCH + b0 + bb) * HDIM + col] = ho;
                }
            }
        } else if (t >= 768 && t < 772) {
            int bb = t - 768;
            float S = s_xscr[bb] + s_xscr[8 + bb] + s_xscr[16 + bb] + s_xscr[24 + bb];
            float Q = s_xscr[4 + bb] + s_xscr[12 + bb] + s_xscr[20 + bb] + s_xscr[28 + bb];
            float mu = S * (1.0f / 768.0f), var = Q * (1.0f / 768.0f) - mu * mu;
            s_xst[nxt * 8 + bb] = mu; s_xst[nxt * 8 + 4 + bb] = rsqrtf(var + 1e-5f);
        }
        __syncthreads();
    }
}

// --------------------------------- launcher ----------------------------------
extern "C" void kernel_launch(void* const* d_in, const int* in_sizes, int n_in,
                              void* d_out, int out_size) {
    const float* x     = (const float*)d_in[0];
    const unsigned char* mask = (const unsigned char*)d_in[1];
    const float* W_emb = (const float*)d_in[2];
    const float* b_emb = (const float*)d_in[3];
    const float* W     = (const float*)d_in[4];
    const float* U     = (const float*)d_in[5];
    const float* bgate = (const float*)d_in[6];
    const float* Wa1   = (const float*)d_in[7];
    const float* Ua1   = (const float*)d_in[8];
    const float* ba1   = (const float*)d_in[9];
    const float* Wa2   = (const float*)d_in[10];
    const float* ba2   = (const float*)d_in[11];
    const float* gammas = (const float*)d_in[12];
    const float* betas  = (const float*)d_in[13];
    float* out = (float*)d_out;

    float *h0, *h1, *xpc, *xa;
    int *srcI;
    cudaGetSymbolAddress((void**)&h0, g_h0);
    cudaGetSymbolAddress((void**)&h1, g_h1);
    cudaGetSymbolAddress((void**)&xpc, g_xpc);
    cudaGetSymbolAddress((void**)&xa, g_xa);
    cudaGetSymbolAddress((void**)&srcI, g_srcI);

    const int scan_smem =
        (ROWS_PER_CTA * WROW_F4 * 4 + 1056 + 768 * 5 + 2 * NBAT * H3 +
         5 * H3 + 192 + 8 + 32 + 16 + 8 + 4 + 4) * 4;
    static int attr_done = 0;
    if (!attr_done) {
        cudaFuncSetAttribute(scan8_kernel, cudaFuncAttributeMaxDynamicSharedMemorySize, scan_smem);
        attr_done = 1;
    }

    // launch order: 0 prep, 1 embed, 2 gemm_xp(compact), 3 SCAN (profiled), ...
    prep_fused<<<H3 + 1, HDIM>>>(U, mask);
    sgemm_kernel<1><<<dim3(HDIM / 64, NROWS / 64), 256>>>(x, W_emb, b_emb, h0, HDIM);

    for (int d = 0; d < DEPTH; d++) {
        float* hin  = (d & 1) ? h1 : h0;
        float* hout = (d & 1) ? h0 : h1;
        sgemm_kernel<3><<<dim3(H3 / 64, NROWS / 64), 256>>>(hin, W, nullptr, xpc, H3);
        scan8_kernel<<<NCLU * CLUSTER_NCTAS, SCAN_THREADS, scan_smem>>>(
            bgate, gammas, betas, hout);
        // xa = hin_full@Wa1 + hprev@Ua1 (fused gather GEMM; no fill needed)
        const int* sI = (d == 0) ? nullptr : (srcI + ((d - 1) & 1) * NROWS);
        gemm_head<<<dim3(ADIM / 64, NROWS / 64), 256>>>(hin, hout, sI, Wa1, Ua1, xa);
        head_kernel<<<NROWS, 128>>>(d, xa, ba1, Wa2, ba2, hout, out, out_size);
        if (d < DEPTH - 1) plan_kernel<<<1, 1024>>>((d + 1) & 1);
    }
}

// round 13
// speedup vs baseline: 1.4908x; 1.0741x over previous
#include <cuda_runtime.h>
#include <cuda_bf16.h>
#include <cstddef>
#include <cstdint>

// Problem constants (fixed by the dataset)
#define BATCH 64
#define LSEQ  512
#define DIN   256
#define HDIM  256
#define H3    768
#define ADIM  128
#define DEPTH 4
#define NROWS (LSEQ * BATCH)   // 32768

// ---- scan: 4-CTA clusters, 2 batches per cluster ----
#define C4_NCTAS   4
#define R4         192         // weight rows per CTA (768/4)
#define NB4        2           // batches per cluster
#define NCLU4      32
#define SCAN_THREADS 896
#define WROW4_F4   65          // 64 data f4 + 1 pad (quad=(row+i)%8 spread)
#define G4_REC     392         // floats per rank record: 192*2 + 4 stats + pad
#define CLUBUF4    (C4_NCTAS * G4_REC)   // 1568 floats per parity
#define SL_STRIDE  520

// hT layout (2 batches): 4 k-blocks of 33 f4 (32 data + 1 pad)
// f4 at block q = k>>6 holds [h(k)b0, h(k)b1, h(k+1)b0, h(k+1)b1] for even k
#define HT2_FLT(c, b) ((((((c) >> 6) * 33) + (((c) & 63) >> 1)) << 2) + (((c) & 1) * 2) + (b))

// ---------------- scratch (device globals; no allocation allowed) -------------
__device__ float g_h0  [(size_t)NROWS * HDIM];
__device__ float g_h1  [(size_t)NROWS * HDIM];
__device__ float g_xpc [(size_t)(NROWS + 64) * H3];  // compacted xp
__device__ float g_xa  [(size_t)NROWS * ADIM];
__device__ float g_Ut  [(size_t)H3 * HDIM];          // U^T (768x256)
__device__ float g_hp  [(size_t)NCLU4 * 2 * CLUBUF4];
__device__ int   g_steplist[BATCH * SL_STRIDE];
__device__ int   g_nsteps[BATCH];
__device__ int   g_off  [BATCH + 1];
__device__ int   g_rowA [NROWS + 64];
__device__ int   g_srcE [NROWS];       // row idx of h before step l (or -1)
__device__ int   g_srcI [2][NROWS];    // row idx of h_full at step l (ping-pong)
__device__ int   g_mtotal;
__device__ unsigned char g_mask[BATCH * LSEQ];

// ---------------------------------- helpers ----------------------------------
__device__ __forceinline__ float warp_sum(float v) {
#pragma unroll
    for (int o = 16; o > 0; o >>= 1) v += __shfl_down_sync(0xffffffffu, v, o);
    return v;
}
__device__ __forceinline__ float fsig(float x) {
    float e = __expf(-x);
    return __fdividef(1.0f, 1.0f + e);
}
__device__ __forceinline__ float ftanhf(float x) {
    float e = __expf(2.0f * x);
    return 1.0f - __fdividef(2.0f, e + 1.0f);
}
__device__ __forceinline__ void fma2(unsigned long long& d, unsigned long long a,
                                     unsigned long long b) {
    asm("fma.rn.f32x2 %0, %1, %2, %0;" : "+l"(d) : "l"(a), "l"(b));
}
__device__ __forceinline__ unsigned long long pk(float lo, float hi) {
    unsigned long long r;
    asm("mov.b64 %0, {%1, %2};" : "=l"(r) : "f"(lo), "f"(hi));
    return r;
}
__device__ __forceinline__ float2 upk(unsigned long long v) {
    float2 r;
    asm("mov.b64 {%0, %1}, %2;" : "=f"(r.x), "=f"(r.y) : "l"(v));
    return r;
}

// ------------- per-batch plan body (lists, offsets, rowA, srcE, srcI) ---------
__device__ __forceinline__ void plan_batch(const unsigned char* m, int b, int ibuf) {
    int n = 0, src = -1;
    for (int l = 0; l < LSEQ; l++) {
        int prev = src;
        if (m[l]) { g_steplist[b * SL_STRIDE + n] = l; n++; src = l; }
        int r = l * BATCH + b;
        g_srcE[r]       = (prev < 0) ? -1 : prev * BATCH + b;
        g_srcI[ibuf][r] = (src  < 0) ? -1 : src  * BATCH + b;
    }
    g_nsteps[b] = n;
    for (int i = n; i <= LSEQ; i++) g_steplist[b * SL_STRIDE + i] = -1;
}

// ----------------- prep: U transpose + mask copy + depth-0 plan ---------------
__global__ void prep_fused(const float* __restrict__ U,
                           const unsigned char* __restrict__ m8) {
    int k = blockIdx.x;
    if (k < H3) {
        int i = threadIdx.x;
        g_Ut[(size_t)k * HDIM + i] = U[(size_t)i * H3 + k];
        return;
    }
    __shared__ unsigned char smm[BATCH * LSEQ];
    __shared__ int mode;
    int t = threadIdx.x;
    if (t == 0) {
        int nz = 0;
        for (int i = 0; i < 64; i++) nz |= m8[4 * i + 1] | m8[4 * i + 2] | m8[4 * i + 3];
        mode = nz ? 1 : 0;
    }
    __syncthreads();
    if (mode) {
        for (int i = t; i < BATCH * LSEQ; i += blockDim.x) {
            unsigned char v = m8[i] ? 1 : 0;
            g_mask[i] = v; smm[i] = v;
        }
    } else {
        const int* m32 = (const int*)m8;
        for (int i = t; i < BATCH * LSEQ; i += blockDim.x) {
            unsigned char v = m32[i] ? 1 : 0;
            g_mask[i] = v; smm[i] = v;
        }
    }
    __syncthreads();
    if (t < BATCH) plan_batch(smm + t * LSEQ, t, 0);
    __syncthreads();
    if (t == 0) {
        int acc = 0;
        for (int b = 0; b < BATCH; b++) { g_off[b] = acc; acc += g_nsteps[b]; }
        g_off[BATCH] = acc;
        g_mtotal = acc;
    }
    __syncthreads();
    if (t < BATCH) {
        int b = t, off = g_off[b], n = g_nsteps[b];
        for (int i = 0; i < n; i++)
            g_rowA[off + i] = g_steplist[b * SL_STRIDE + i] * BATCH + b;
    }
}

// ---------------- plan (d>=1): one block, everything ---------------------------
__global__ void plan_kernel(int ibuf) {
    __shared__ unsigned char smm[BATCH * LSEQ];
    int t = threadIdx.x;   // 1024
    for (int i = t; i < BATCH * LSEQ; i += blockDim.x) smm[i] = g_mask[i];
    __syncthreads();
    if (t < BATCH) plan_batch(smm + t * LSEQ, t, ibuf);
    __syncthreads();
    if (t == 0) {
        int acc = 0;
        for (int b = 0; b < BATCH; b++) { g_off[b] = acc; acc += g_nsteps[b]; }
        g_off[BATCH] = acc;
        g_mtotal = acc;
    }
    __syncthreads();
    if (t < BATCH) {
        int b = t, off = g_off[b], n = g_nsteps[b];
        for (int i = 0; i < n; i++)
            g_rowA[off + i] = g_steplist[b * SL_STRIDE + i] * BATCH + b;
    }
}

// ------------------------------- tiled SGEMM (f32x2) --------------------------
// MODE 1: A row r -> x[b=r&63][l=r>>6] (embed). MODE 3: gather g_rowA[r].
template <int MODE>
__global__ void __launch_bounds__(256) sgemm_kernel(
    const float* __restrict__ A, const float* __restrict__ Bm,
    const float* __restrict__ bias, float* __restrict__ C, int N) {
    const int K = 256;
    __shared__ __align__(16) float Ast[16][68];
    __shared__ __align__(16) float Bs[16][64];
    int t  = threadIdx.x;
    int m0 = blockIdx.y * 64;
    int n0 = blockIdx.x * 64;
    if (MODE == 3 && m0 >= g_mtotal) return;
    int ty = t >> 4, tx = t & 15;

    unsigned long long acc2[4][2];
#pragma unroll
    for (int i = 0; i < 4; i++) { acc2[i][0] = 0ull; acc2[i][1] = 0ull; }

    int ar = t >> 2;
    int ak = (t & 3) * 4;
    int arow = m0 + ar;
    const float* Aptr;
    if (MODE == 1) {
        int b = arow & 63, l = arow >> 6;
        Aptr = A + ((size_t)b * LSEQ + l) * K;
    } else {
        int mt = g_mtotal;
        int rr = (arow < mt) ? arow : (mt - 1);
        Aptr = A + (size_t)g_rowA[rr] * K;
    }
    int bk = t >> 4;
    int bn = (t & 15) * 4;

    for (int k0 = 0; k0 < K; k0 += 16) {
        float4 av = *(const float4*)(Aptr + k0 + ak);
        Ast[ak + 0][ar] = av.x;
        Ast[ak + 1][ar] = av.y;
        Ast[ak + 2][ar] = av.z;
        Ast[ak + 3][ar] = av.w;
        *(float4*)(&Bs[bk][bn]) = *(const float4*)(Bm + (size_t)(k0 + bk) * N + n0 + bn);
        __syncthreads();
#pragma unroll
        for (int kk = 0; kk < 16; kk++) {
            float4 a  = *(const float4*)(&Ast[kk][ty * 4]);
            float4 bb = *(const float4*)(&Bs[kk][tx * 4]);
            unsigned long long b01 = pk(bb.x, bb.y), b23 = pk(bb.z, bb.w);
            unsigned long long ax = pk(a.x, a.x), ay = pk(a.y, a.y);
            unsigned long long az = pk(a.z, a.z), aw = pk(a.w, a.w);
            fma2(acc2[0][0], ax, b01); fma2(acc2[0][1], ax, b23);
            fma2(acc2[1][0], ay, b01); fma2(acc2[1][1], ay, b23);
            fma2(acc2[2][0], az, b01); fma2(acc2[2][1], az, b23);
            fma2(acc2[3][0], aw, b01); fma2(acc2[3][1], aw, b23);
        }
        __syncthreads();
    }
#pragma unroll
    for (int i = 0; i < 4; i++) {
        int row = m0 + ty * 4 + i;
        float2 v01 = upk(acc2[i][0]), v23 = upk(acc2[i][1]);
        float4 v;
        v.x = v01.x; v.y = v01.y; v.z = v23.x; v.w = v23.y;
        if (bias) {
            v.x += bias[n0 + tx * 4 + 0];
            v.y += bias[n0 + tx * 4 + 1];
            v.z += bias[n0 + tx * 4 + 2];
            v.w += bias[n0 + tx * 4 + 3];
        }
        *(float4*)(&C[(size_t)row * N + n0 + tx * 4]) = v;
    }
}

// -------- head GEMM: xa = hA[srcI]@Wa1 + hB[srcE]@Ua1 (K=512 fused gather) ----
__global__ void __launch_bounds__(256) gemm_head(
    const float* __restrict__ hA, const float* __restrict__ hB,
    const int* __restrict__ srcI,      // null => identity
    const float* __restrict__ Wa1, const float* __restrict__ Ua1,
    float* __restrict__ xa) {
    const int K = 256, N = ADIM;
    __shared__ __align__(16) float Ast[16][68];
    __shared__ __align__(16) float Bs[16][64];
    int t  = threadIdx.x;
    int m0 = blockIdx.y * 64;
    int n0 = blockIdx.x * 64;
    int ty = t >> 4, tx = t & 15;

    unsigned long long acc2[4][2];
#pragma unroll
    for (int i = 0; i < 4; i++) { acc2[i][0] = 0ull; acc2[i][1] = 0ull; }

    int ar = t >> 2;
    int ak = (t & 3) * 4;
    int arow = m0 + ar;
    int si = srcI ? srcI[arow] : arow;
    int se = g_srcE[arow];
    const float* pA = hA + (size_t)((si < 0) ? 0 : si) * K;
    const float* pB = hB + (size_t)((se < 0) ? 0 : se) * K;
    int bk = t >> 4;
    int bn = (t & 15) * 4;

#pragma unroll
    for (int pass = 0; pass < 2; pass++) {
        const float* Ap = (pass == 0) ? pA : pB;
        const bool valid = (pass == 0) ? (si >= 0) : (se >= 0);
        const float* Bp = (pass == 0) ? Wa1 : Ua1;
        for (int k0 = 0; k0 < K; k0 += 16) {
            float4 av = make_float4(0.f, 0.f, 0.f, 0.f);
            if (valid) av = *(const float4*)(Ap + k0 + ak);
            Ast[ak + 0][ar] = av.x;
            Ast[ak + 1][ar] = av.y;
            Ast[ak + 2][ar] = av.z;
            Ast[ak + 3][ar] = av.w;
            *(float4*)(&Bs[bk][bn]) = *(const float4*)(Bp + (size_t)(k0 + bk) * N + n0 + bn);
            __syncthreads();
#pragma unroll
            for (int kk = 0; kk < 16; kk++) {
                float4 a  = *(const float4*)(&Ast[kk][ty * 4]);
                float4 bb = *(const float4*)(&Bs[kk][tx * 4]);
                unsigned long long b01 = pk(bb.x, bb.y), b23 = pk(bb.z, bb.w);
                unsigned long long ax = pk(a.x, a.x), ay = pk(a.y, a.y);
                unsigned long long az = pk(a.z, a.z), aw = pk(a.w, a.w);
                fma2(acc2[0][0], ax, b01); fma2(acc2[0][1], ax, b23);
                fma2(acc2[1][0], ay, b01); fma2(acc2[1][1], ay, b23);
                fma2(acc2[2][0], az, b01); fma2(acc2[2][1], az, b23);
                fma2(acc2[3][0], aw, b01); fma2(acc2[3][1], aw, b23);
            }
            __syncthreads();
        }
    }
#pragma unroll
    for (int i = 0; i < 4; i++) {
        int row = m0 + ty * 4 + i;
        float2 v01 = upk(acc2[i][0]), v23 = upk(acc2[i][1]);
        float4 v;
        v.x = v01.x; v.y = v01.y; v.z = v23.x; v.w = v23.y;
        *(float4*)(&xa[(size_t)row * N + n0 + tx * 4]) = v;
    }
}

// -------------------- head: bulk action/policy + next mask --------------------
__global__ void head_kernel(int d, const float* __restrict__ lin,
                            const float* __restrict__ ba1,
                            const float* __restrict__ Wa2,
                            const float* __restrict__ ba2,
                            const float* __restrict__ hout,
                            float* __restrict__ out, int out_size) {
    int r = blockIdx.x;
    int l = r >> 6, b = r & 63;
    int t = threadIdx.x;           // 128
    __shared__ float s[8];

    float v = tanhf(lin[(size_t)r * ADIM + t] + ba1[t]);
    float p0 = warp_sum(v * Wa2[2 * t]);
    float p1 = warp_sum(v * Wa2[2 * t + 1]);
    if ((t & 31) == 0) { s[(t >> 5) * 2] = p0; s[(t >> 5) * 2 + 1] = p1; }

    if (d == DEPTH - 1 && l == LSEQ - 1 && out_size >= BATCH * HDIM) {
        int n = g_nsteps[b];
        int last = (n > 0) ? g_steplist[b * SL_STRIDE + n - 1] : -1;
        if (last >= 0) {
            const float* hr = hout + ((size_t)last * BATCH + b) * HDIM;
            out[b * HDIM + t]       = hr[t];
            out[b * HDIM + 128 + t] = hr[128 + t];
        } else {
            out[b * HDIM + t]       = 0.0f;
            out[b * HDIM + 128 + t] = 0.0f;
        }
    }
    __syncthreads();
    if (t == 0) {
        float l0 = s[0] + s[2] + s[4] + s[6] + ba2[0];
        float l1 = s[1] + s[3] + s[5] + s[7] + ba2[1];
        unsigned char mt = g_mask[b * LSEQ + l];
        unsigned char act = ((l1 > l0) && mt) ? 1 : 0;
        g_mask[b * LSEQ + l] = act;
        if (out_size >= 409600) {
            float m = fmaxf(l0, l1);
            float e0 = expf(l0 - m), e1 = expf(l1 - m);
            float inv = 1.0f / (e0 + e1);
            size_t ai = (size_t)BATCH * HDIM + ((size_t)(b * DEPTH + d)) * LSEQ + l;
            out[ai] = act ? 1.0f : 0.0f;
            size_t pi = (size_t)BATCH * HDIM + (size_t)BATCH * DEPTH * LSEQ +
                        (((size_t)(b * DEPTH + d)) * LSEQ + l) * 2;
            out[pi]     = e0 * inv;
            out[pi + 1] = e1 * inv;
        }
    }
}

// ----------- cluster scan: 4-CTA clusters, 2 batches, compacted xp ------------
// Each CTA holds 192 rows of U^T (195KB smem, 65-f4 padded rows). One cluster
// barrier per iteration; 4-record L2 exchange; gates = 512 single items.
// LN/gate constants read via __ldg (L1-resident within launch).
__global__ void __cluster_dims__(C4_NCTAS, 1, 1) __launch_bounds__(SCAN_THREADS, 1)
scan9_kernel(const float* __restrict__ bg,
             const float* __restrict__ gammas,
             const float* __restrict__ betas,
             float* __restrict__ hout) {
    extern __shared__ __align__(16) float sm[];
    float* Wsm   = sm;                         // 192*65*4 = 49920 floats
    float* s_hT  = Wsm + R4 * WROW4_F4 * 4;    // 528
    float* s_hp  = s_hT + 528;                 // 768*3 = 2304
    float* s_xpa = s_hp + 2304;                // 2*2*768 = 3072
    float* s_lnA = s_xpa + 3072;               // 24*4 = 96
    float* s_stat= s_lnA + 96;                 // 4 (2 b x mu,rstd)
    float* s_xst = s_stat + 4;                 // 8 (2 par x 2 b x mu,rstd)
    int*   s_lb  = (int*)(s_xst + 8);          // 4 (2 par x 2 b)
    int*   s_off = s_lb + 4;                   // 2
    int*   s_ns  = s_off + 2;                  // 2

    const int t    = threadIdx.x;
    const int rank = blockIdx.x & (C4_NCTAS - 1);
    const int clu  = blockIdx.x >> 2;
    const int b0   = clu * NB4;
    const int lane = t & 31, wid = t >> 5;

    // ---- weight slice (rows 192*rank..+191 of U^T), 65-f4 padded rows ----
    {
        const float4* src = (const float4*)(g_Ut + (size_t)(R4 * rank) * HDIM);
        float4* dst = (float4*)Wsm;
        for (int i = t; i < R4 * 64; i += SCAN_THREADS) {
            int row = i >> 6, c4 = i & 63;
            dst[row * WROW4_F4 + c4] = src[(size_t)row * 64 + c4];
        }
    }
    for (int i = t; i < 528; i += SCAN_THREADS) s_hT[i] = 0.0f;

    int maxit = 0;
#pragma unroll
    for (int i = 0; i < NB4; i++) {
        int n = g_nsteps[b0 + i];
        maxit = (n > maxit) ? n : maxit;
    }
    if (t < NB4) {
        s_lb[t]  = g_steplist[(b0 + t) * SL_STRIDE];
        s_off[t] = g_off[b0 + t];
        s_ns[t]  = g_nsteps[b0 + t];
    }
    __syncthreads();

    // prologue: xp(it=0) for 2 batches (384 f4)
    if (t < 384) {
        int bb = t / 192, c4 = t - 192 * bb;
        if (s_ns[bb] > 0)
            ((float4*)s_xpa)[t] =
                *((const float4*)g_xpc + (size_t)s_off[bb] * 192 + c4);
    }
    __syncthreads();
    if (t >= 768 && t < 832) {   // warps 24,25: xp stats it=0
        int u = t - 768, bb = u >> 5;
        const float* xr = s_xpa + bb * H3;
        float s = 0.f, q = 0.f;
#pragma unroll
        for (int j = 0; j < 24; j++) { float v = xr[(u & 31) + 32 * j]; s += v; q += v * v; }
        s = warp_sum(s); q = warp_sum(q);
        if ((u & 31) == 0) {
            float mu = s * (1.0f / 768.0f), var = q * (1.0f / 768.0f) - mu * mu;
            s_xst[bb * 2] = mu; s_xst[bb * 2 + 1] = rsqrtf(var + 1e-5f);
        }
    }
    __syncthreads();

    // matvec mapping: thread = (row r_, K-quarter kq)
    const int r_ = t >> 2, kq = t & 3;
    const float4* wf = (const float4*)Wsm + r_ * WROW4_F4 + kq * 16;
    const float4* ht = (const float4*)s_hT + kq * 33;
    float* gbase = g_hp + (size_t)clu * (2 * CLUBUF4);

    for (int it = 0; it < maxit; ++it) {
        const int par = it & 1, nxt = par ^ 1;
        float* gout = gbase + par * CLUBUF4;

        // ================ phase A ================
        float4 pf0, pf1, pf2;
        if (t < 768) {
            float d0 = 0.f, d1 = 0.f;
#pragma unroll
            for (int i = 0; i < 16; i++) {
                float4 w  = wf[i];
                float4 h0 = ht[i * 2 + 0];   // [h(k)b0,h(k)b1,h(k+1)b0,h(k+1)b1]
                float4 h1 = ht[i * 2 + 1];
                d0 += w.x * h0.x + w.y * h0.z;
                d1 += w.x * h0.y + w.y * h0.w;
                d0 += w.z * h1.x + w.w * h1.z;
                d1 += w.z * h1.y + w.w * h1.w;
            }
            // reduce over 4 K-quarters (lanes adjacent)
            d0 += __shfl_xor_sync(0xffffffffu, d0, 1);
            d1 += __shfl_xor_sync(0xffffffffu, d1, 1);
            d0 += __shfl_xor_sync(0xffffffffu, d0, 2);
            d1 += __shfl_xor_sync(0xffffffffu, d1, 2);
            if (kq == 0)
                ((float2*)gout)[rank * (G4_REC / 2) + r_] = make_float2(d0, d1);
            // LN partials: sum over this warp's 8 rows (bits 2..4 of lane)
            float q0 = d0 * d0, q1 = d1 * d1;
#pragma unroll
            for (int m = 4; m <= 16; m <<= 1) {
                d0 += __shfl_xor_sync(0xffffffffu, d0, m);
                d1 += __shfl_xor_sync(0xffffffffu, d1, m);
                q0 += __shfl_xor_sync(0xffffffffu, q0, m);
                q1 += __shfl_xor_sync(0xffffffffu, q1, m);
            }
            if (lane == 0) {
                s_lnA[wid * 4 + 0] = d0; s_lnA[wid * 4 + 1] = d1;
                s_lnA[wid * 4 + 2] = q0; s_lnA[wid * 4 + 3] = q1;
            }
        } else {
            // helpers: next step indices + prefetch compacted xp(it+1)
            int u = t - 768;
            if (u < NB4) s_lb[nxt * NB4 + u] = g_steplist[(b0 + u) * SL_STRIDE + it + 1];
            const float4* xpf4 = (const float4*)g_xpc;
#pragma unroll
            for (int j = 0; j < 3; j++) {
                int idx = u + 128 * j;        // 0..383
                int bb = idx / 192, c4 = idx - 192 * bb;
                float4 vv = make_float4(0.f, 0.f, 0.f, 0.f);
                if (it + 1 < s_ns[bb])
                    vv = xpf4[(size_t)(s_off[bb] + it + 1) * 192 + c4];
                if (j == 0) pf0 = vv; else if (j == 1) pf1 = vv; else pf2 = vv;
            }
        }
        __syncthreads();
        if (t < 4) {
            float acc = 0.f;
#pragma unroll
            for (int w = 0; w < 24; w++) acc += s_lnA[w * 4 + t];
            gout[rank * G4_REC + 384 + t] = acc;   // [Sd0, Sd1, Sq0, Sq1]
        }

        asm volatile("barrier.cluster.arrive.aligned;" ::: "memory");
        asm volatile("barrier.cluster.wait.aligned;" ::: "memory");

        // ============ gather phase ============
        if (t < 768) {
            int rank_r = t / R4, wrow_r = t - R4 * rank_r;
            float2 v;
            {
                const float2* gp = (const float2*)(gbase + par * CLUBUF4);
                float2 raw;
                raw.x = __ldcv(&((const float*)gp)[(rank_r * (G4_REC / 2) + wrow_r) * 2]);
                raw.y = __ldcv(&((const float*)gp)[(rank_r * (G4_REC / 2) + wrow_r) * 2 + 1]);
                v = raw;
            }
            s_hp[t * 3]     = v.x;
            s_hp[t * 3 + 1] = v.y;
            if (t < 2) {   // hp LN stats for batch t
                float S = 0.f, Q = 0.f;
#pragma unroll
                for (int rr = 0; rr < 4; rr++) {
                    S += __ldcv(gout + rr * G4_REC + 384 + t);
                    Q += __ldcv(gout + rr * G4_REC + 386 + t);
                }
                float mu  = S * (1.0f / 768.0f);
                float var = Q * (1.0f / 768.0f) - mu * mu;
                s_stat[t * 2]     = mu;
                s_stat[t * 2 + 1] = rsqrtf(var + 1e-5f);
            }
        } else {
            int u = t - 768;
            float4* xd = (float4*)(s_xpa + nxt * (NB4 * H3));
            xd[u + 0]   = pf0;
            xd[u + 128] = pf1;
            xd[u + 256] = pf2;
        }
        __syncthreads();

        // ============ gates (t<512, one item) | xp-stats for nxt (2 warps) =====
        if (t < 512) {
            int bb = t >> 8, col = t & 255;
            int lb = s_lb[par * NB4 + bb];
            if (lb >= 0) {
                float mu = s_stat[bb * 2], rs = s_stat[bb * 2 + 1];
                float mux = s_xst[par * 4 + bb * 2], rsx = s_xst[par * 4 + bb * 2 + 1];
                const float* xr = s_xpa + par * (NB4 * H3) + bb * H3;
                float x0 = __ldg(gammas + col)       * (xr[col]       - mux) * rsx + __ldg(betas + col);
                float x1 = __ldg(gammas + col + 256) * (xr[col + 256] - mux) * rsx + __ldg(betas + col + 256);
                float x2 = __ldg(gammas + col + 512) * (xr[col + 512] - mux) * rsx + __ldg(betas + col + 512);
                float hp0 = (s_hp[col * 3 + bb]         - mu) * rs * __ldg(gammas + H3 + col)       + __ldg(betas + H3 + col);
                float hp1 = (s_hp[(col + 256) * 3 + bb] - mu) * rs * __ldg(gammas + H3 + col + 256) + __ldg(betas + H3 + col + 256);
                float hp2 = (s_hp[(col + 512) * 3 + bb] - mu) * rs * __ldg(gammas + H3 + col + 512) + __ldg(betas + H3 + col + 512);
                float r  = fsig(x0 + hp0     + __ldg(bg + col));
                float z  = fsig(x1 + hp1     + __ldg(bg + col + 256));
                float hh = ftanhf(x2 + r * hp2 + __ldg(bg + col + 512));
                float hold = s_hT[HT2_FLT(col, bb)];
                float ho = z * hold + (1.0f - z) * hh;
                s_hT[HT2_FLT(col, bb)] = ho;
                if (rank == bb)
                    hout[((size_t)lb * BATCH + b0 + bb) * HDIM + col] = ho;
            }
        } else if (t >= 768 && t < 832) {
            int u = t - 768, bb = u >> 5;
            const float* xr = s_xpa + nxt * (NB4 * H3) + bb * H3;
            float s = 0.f, q = 0.f;
#pragma unroll
            for (int j = 0; j < 24; j++) { float v = xr[(u & 31) + 32 * j]; s += v; q += v * v; }
            s = warp_sum(s); q = warp_sum(q);
            if ((u & 31) == 0) {
                float mu = s * (1.0f / 768.0f), var = q * (1.0f / 768.0f) - mu * mu;
                s_xst[nxt * 4 + bb * 2] = mu;
                s_xst[nxt * 4 + bb * 2 + 1] = rsqrtf(var + 1e-5f);
            }
        }
        __syncthreads();   // s_hT / s_lb / s_xpa / s_xst stable for next iter
    }
}

// --------------------------------- launcher ----------------------------------
extern "C" void kernel_launch(void* const* d_in, const int* in_sizes, int n_in,
                              void* d_out, int out_size) {
    const float* x     = (const float*)d_in[0];
    const unsigned char* mask = (const unsigned char*)d_in[1];
    const float* W_emb = (const float*)d_in[2];
    const float* b_emb = (const float*)d_in[3];
    const float* W     = (const float*)d_in[4];
    const float* U     = (const float*)d_in[5];
    const float* bgate = (const float*)d_in[6];
    const float* Wa1   = (const float*)d_in[7];
    const float* Ua1   = (const float*)d_in[8];
    const float* ba1   = (const float*)d_in[9];
    const float* Wa2   = (const float*)d_in[10];
    const float* ba2   = (const float*)d_in[11];
    const float* gammas = (const float*)d_in[12];
    const float* betas  = (const float*)d_in[13];
    float* out = (float*)d_out;

    float *h0, *h1, *xpc, *xa;
    int *srcI;
    cudaGetSymbolAddress((void**)&h0, g_h0);
    cudaGetSymbolAddress((void**)&h1, g_h1);
    cudaGetSymbolAddress((void**)&xpc, g_xpc);
    cudaGetSymbolAddress((void**)&xa, g_xa);
    cudaGetSymbolAddress((void**)&srcI, g_srcI);

    const int scan_smem =
        (R4 * WROW4_F4 * 4 + 528 + 2304 + 3072 + 96 + 4 + 8 + 4 + 2 + 2) * 4;
    static int attr_done = 0;
    if (!attr_done) {
        cudaFuncSetAttribute(scan9_kernel, cudaFuncAttributeMaxDynamicSharedMemorySize, scan_smem);
        attr_done = 1;
    }

    // launch order: 0 prep, 1 embed, 2 gemm_xp(compact), 3 SCAN (profiled), ...
    prep_fused<<<H3 + 1, HDIM>>>(U, mask);
    sgemm_kernel<1><<<dim3(HDIM / 64, NROWS / 64), 256>>>(x, W_emb, b_emb, h0, HDIM);

    for (int d = 0; d < DEPTH; d++) {
        float* hin  = (d & 1) ? h1 : h0;
        float* hout = (d & 1) ? h0 : h1;
        sgemm_kernel<3><<<dim3(H3 / 64, NROWS / 64), 256>>>(hin, W, nullptr, xpc, H3);
        scan9_kernel<<<NCLU4 * C4_NCTAS, SCAN_THREADS, scan_smem>>>(
            bgate, gammas, betas, hout);
        const int* sI = (d == 0) ? nullptr : (srcI + ((d - 1) & 1) * NROWS);
        gemm_head<<<dim3(ADIM / 64, NROWS / 64), 256>>>(hin, hout, sI, Wa1, Ua1, xa);
        head_kernel<<<NROWS, 128>>>(d, xa, ba1, Wa2, ba2, hout, out, out_size);
        if (d < DEPTH - 1) plan_kernel<<<1, 1024>>>((d + 1) & 1);
    }
}